// round 2
// baseline (speedup 1.0000x reference)
#include <cuda_runtime.h>
#include <math.h>
#include <stdint.h>

// Problem constants
#define BB   8
#define SEQ  1024
#define DIM  768
#define NH   12
#define KG   4
#define HD   64
#define QKD  256          // KG*HD : effective QK head dim after mix-fold
#define MTOT (BB*SEQ)     // 8192

// Scratch (static device globals — no runtime allocation allowed)
__device__ float g_qk[(size_t)MTOT * 512];   // per row: [0,256)=q heads, [256,512)=k heads
__device__ float g_v [(size_t)MTOT * DIM];
__device__ float g_ctx[(size_t)MTOT * DIM];

// ---------------------------------------------------------------------------
// SGEMM: C[M, NC] = A[M, 768] @ W[NC, 768]^T (+ bias). Both operands K-major.
// 128x128 block tile, 8x8 per thread (split 64+64 fragments), 256 threads.
// ---------------------------------------------------------------------------
template<int NC, bool BIAS>
__global__ void __launch_bounds__(256) sgemm_nt_k(const float* __restrict__ A,
                                                  const float* __restrict__ W,
                                                  const float* __restrict__ bias,
                                                  float* __restrict__ C)
{
    __shared__ float As[8][128];
    __shared__ float Ws[8][128];

    const int m0  = blockIdx.y * 128;
    const int n0  = blockIdx.x * 128;
    const int tid = threadIdx.x;
    const int ty  = tid >> 4;        // 0..15
    const int tx  = tid & 15;        // 0..15
    const int lr  = tid >> 1;        // 0..127 (row within tile for loads)
    const int lk  = (tid & 1) * 4;   // 0 or 4

    const float* Ap = A + (size_t)(m0 + lr) * DIM + lk;
    const float* Wp = W + (size_t)(n0 + lr) * DIM + lk;

    float acc[8][8];
#pragma unroll
    for (int r = 0; r < 8; r++)
#pragma unroll
        for (int c = 0; c < 8; c++) acc[r][c] = 0.f;

    for (int k0 = 0; k0 < DIM; k0 += 8) {
        float4 av = *(const float4*)(Ap + k0);
        float4 wv = *(const float4*)(Wp + k0);
        __syncthreads();  // previous iteration's reads complete
        As[lk + 0][lr] = av.x; As[lk + 1][lr] = av.y;
        As[lk + 2][lr] = av.z; As[lk + 3][lr] = av.w;
        Ws[lk + 0][lr] = wv.x; Ws[lk + 1][lr] = wv.y;
        Ws[lk + 2][lr] = wv.z; Ws[lk + 3][lr] = wv.w;
        __syncthreads();
#pragma unroll
        for (int kk = 0; kk < 8; kk++) {
            float a[8], w[8];
            *(float4*)(a)     = *(const float4*)&As[kk][ty * 4];
            *(float4*)(a + 4) = *(const float4*)&As[kk][64 + ty * 4];
            *(float4*)(w)     = *(const float4*)&Ws[kk][tx * 4];
            *(float4*)(w + 4) = *(const float4*)&Ws[kk][64 + tx * 4];
#pragma unroll
            for (int r = 0; r < 8; r++)
#pragma unroll
                for (int c = 0; c < 8; c++)
                    acc[r][c] += a[r] * w[c];
        }
    }

#pragma unroll
    for (int r = 0; r < 8; r++) {
        const int row = m0 + ((r < 4) ? (ty * 4 + r) : (64 + ty * 4 + r - 4));
#pragma unroll
        for (int cg = 0; cg < 2; cg++) {
            const int col = n0 + ((cg == 0) ? (tx * 4) : (64 + tx * 4));
            float4 o;
            o.x = acc[r][cg * 4 + 0]; o.y = acc[r][cg * 4 + 1];
            o.z = acc[r][cg * 4 + 2]; o.w = acc[r][cg * 4 + 3];
            if (BIAS) {
                const float4 bv = *(const float4*)&bias[col];
                o.x += bv.x; o.y += bv.y; o.z += bv.z; o.w += bv.w;
            }
            *(float4*)&C[(size_t)row * NC + col] = o;
        }
    }
}

// ---------------------------------------------------------------------------
// Fused FiSH attention: per (b, h, 64-row i-tile), flash-style online softmax.
//   Q'[i, 256] = mix[h,k] * scale * q_k[i]   (folded into smem load)
//   S = Q' K^T ; P = softmax_online(S) ; O += P V
// 256 threads; thread (ty,tx) owns rows {ty+16r} x cols {tx+16c}, 4x4 each.
// ---------------------------------------------------------------------------
#define QS_STR 260   // 256 + 4 pad (16B-aligned rows, spreads banks)
#define VS_STR 68
#define PS_STR 68

__global__ void __launch_bounds__(256) fish_attn_k(const float* __restrict__ mixl,
                                                   float* __restrict__ ctx)
{
    extern __shared__ float sm[];
    float* Qs = sm;                       // [64][QS_STR]
    float* Ks = Qs + 64 * QS_STR;         // [64][QS_STR]
    float* Vs = Ks + 64 * QS_STR;         // [64][VS_STR]
    float* Ps = Vs + 64 * VS_STR;         // [64][PS_STR]

    const int i0  = blockIdx.x * 64;
    const int h   = blockIdx.y;
    const int b   = blockIdx.z;
    const int tid = threadIdx.x;
    const int ty  = tid >> 4;   // 0..15
    const int tx  = tid & 15;   // 0..15

    // mix = softmax(mix_logits[h, :]) , fold in HEAD_DIM^-0.5
    float ml0 = mixl[h * KG + 0], ml1 = mixl[h * KG + 1];
    float ml2 = mixl[h * KG + 2], ml3 = mixl[h * KG + 3];
    float mm = fmaxf(fmaxf(ml0, ml1), fmaxf(ml2, ml3));
    float e0 = expf(ml0 - mm), e1 = expf(ml1 - mm);
    float e2 = expf(ml2 - mm), e3 = expf(ml3 - mm);
    float inv_es = 0.125f / (e0 + e1 + e2 + e3);
    float mixw[KG] = {e0 * inv_es, e1 * inv_es, e2 * inv_es, e3 * inv_es};

    // Load + scale Q' tile (once per block)
    {
        const int c = (tid & 63) * 4;       // 0..252 step 4, within one head
        const float s = mixw[c >> 6];
        for (int i = tid >> 6; i < 64; i += 4) {
            float4 q = *(const float4*)&g_qk[((size_t)(b * SEQ + i0 + i)) * 512 + c];
            q.x *= s; q.y *= s; q.z *= s; q.w *= s;
            *(float4*)&Qs[i * QS_STR + c] = q;
        }
    }

    float m_r[4], l_r[4], o[4][4];
#pragma unroll
    for (int r = 0; r < 4; r++) {
        m_r[r] = -INFINITY; l_r[r] = 0.f;
#pragma unroll
        for (int c = 0; c < 4; c++) o[r][c] = 0.f;
    }

    for (int j0 = 0; j0 < SEQ; j0 += 64) {
        __syncthreads();   // prior AV reads done (and first iter: Q store visible below)
        // Load K tile
        {
            const int c = (tid & 63) * 4;
            for (int j = tid >> 6; j < 64; j += 4)
                *(float4*)&Ks[j * QS_STR + c] =
                    *(const float4*)&g_qk[((size_t)(b * SEQ + j0 + j)) * 512 + 256 + c];
        }
        // Load V tile (head h slice)
        {
            const int d = (tid & 15) * 4;
            for (int j = tid >> 4; j < 64; j += 16)
                *(float4*)&Vs[j * VS_STR + d] =
                    *(const float4*)&g_v[((size_t)(b * SEQ + j0 + j)) * DIM + h * HD + d];
        }
        __syncthreads();

        // S = Q' K^T  (4x4 per thread)
        float s_[4][4];
#pragma unroll
        for (int r = 0; r < 4; r++)
#pragma unroll
            for (int c = 0; c < 4; c++) s_[r][c] = 0.f;

        for (int kk = 0; kk < QKD; kk += 4) {
            float4 qf[4], kf[4];
#pragma unroll
            for (int r = 0; r < 4; r++)
                qf[r] = *(const float4*)&Qs[(ty + 16 * r) * QS_STR + kk];
#pragma unroll
            for (int c = 0; c < 4; c++)
                kf[c] = *(const float4*)&Ks[(tx + 16 * c) * QS_STR + kk];
#pragma unroll
            for (int r = 0; r < 4; r++)
#pragma unroll
                for (int c = 0; c < 4; c++)
                    s_[r][c] += qf[r].x * kf[c].x + qf[r].y * kf[c].y
                              + qf[r].z * kf[c].z + qf[r].w * kf[c].w;
        }

        // Online softmax per row (reduce across the 16 tx lanes; same-warp groups)
#pragma unroll
        for (int r = 0; r < 4; r++) {
            float mx = fmaxf(fmaxf(s_[r][0], s_[r][1]), fmaxf(s_[r][2], s_[r][3]));
#pragma unroll
            for (int off = 8; off >= 1; off >>= 1)
                mx = fmaxf(mx, __shfl_xor_sync(0xffffffffu, mx, off));
            const float mnew = fmaxf(m_r[r], mx);
            const float corr = __expf(m_r[r] - mnew);
            float rs = 0.f;
#pragma unroll
            for (int c = 0; c < 4; c++) {
                s_[r][c] = __expf(s_[r][c] - mnew);
                rs += s_[r][c];
            }
#pragma unroll
            for (int off = 8; off >= 1; off >>= 1)
                rs += __shfl_xor_sync(0xffffffffu, rs, off);
            l_r[r] = l_r[r] * corr + rs;
            m_r[r] = mnew;
#pragma unroll
            for (int c = 0; c < 4; c++) {
                o[r][c] *= corr;
                Ps[(ty + 16 * r) * PS_STR + (tx + 16 * c)] = s_[r][c];
            }
        }
        __syncwarp();   // P rows are produced & consumed within the same warp

        // O += P V
        for (int jj = 0; jj < 64; jj += 4) {
            float p4[4][4];
#pragma unroll
            for (int r = 0; r < 4; r++)
                *(float4*)p4[r] = *(const float4*)&Ps[(ty + 16 * r) * PS_STR + jj];
#pragma unroll
            for (int q = 0; q < 4; q++) {
                float vq[4];
#pragma unroll
                for (int c = 0; c < 4; c++)
                    vq[c] = Vs[(jj + q) * VS_STR + tx + 16 * c];
#pragma unroll
                for (int r = 0; r < 4; r++)
#pragma unroll
                    for (int c = 0; c < 4; c++)
                        o[r][c] += p4[r][q] * vq[c];
            }
        }
    }

    // Normalize and write ctx in (B, N, 768) layout
#pragma unroll
    for (int r = 0; r < 4; r++) {
        const float inv = 1.f / l_r[r];
        const size_t rowoff = ((size_t)(b * SEQ + i0 + ty + 16 * r)) * DIM + h * HD;
#pragma unroll
        for (int c = 0; c < 4; c++)
            ctx[rowoff + tx + 16 * c] = o[r][c] * inv;
    }
}

// ---------------------------------------------------------------------------
// Launch
// ---------------------------------------------------------------------------
extern "C" void kernel_launch(void* const* d_in, const int* in_sizes, int n_in,
                              void* d_out, int out_size)
{
    const float* x      = (const float*)d_in[0];
    const float* w_qkv  = (const float*)d_in[1];
    const float* mixl   = (const float*)d_in[2];
    const float* w_v    = (const float*)d_in[3];
    const float* w_proj = (const float*)d_in[4];
    const float* b_proj = (const float*)d_in[5];
    float* out = (float*)d_out;

    float *qk, *v, *ctx;
    cudaGetSymbolAddress((void**)&qk,  g_qk);
    cudaGetSymbolAddress((void**)&v,   g_v);
    cudaGetSymbolAddress((void**)&ctx, g_ctx);

    const int attn_smem = (64 * QS_STR * 2 + 64 * VS_STR + 64 * PS_STR) * (int)sizeof(float);
    cudaFuncSetAttribute(fish_attn_k, cudaFuncAttributeMaxDynamicSharedMemorySize, attn_smem);

    // 1) qk = x @ w_qkv[0:512]^T   (q and k global heads; v-slice unused by reference)
    sgemm_nt_k<512, false><<<dim3(4, 64), 256>>>(x, w_qkv, nullptr, qk);
    // 2) v = x @ w_v^T
    sgemm_nt_k<768, false><<<dim3(6, 64), 256>>>(x, w_v, nullptr, v);
    // 3) fused mix + attention
    fish_attn_k<<<dim3(SEQ / 64, NH, BB), 256, attn_smem>>>(mixl, ctx);
    // 4) out = ctx @ w_proj^T + b_proj
    sgemm_nt_k<768, true><<<dim3(6, 64), 256>>>(ctx, w_proj, b_proj, out);
}

// round 3
// speedup vs baseline: 1.9172x; 1.9172x over previous
#include <cuda_runtime.h>
#include <math.h>
#include <stdint.h>

// Problem constants
#define BB   8
#define SEQ  1024
#define DIM  768
#define NH   12
#define KG   4
#define HD   64
#define QKD  256          // KG*HD : effective QK head dim after mix-fold
#define MTOT (BB*SEQ)     // 8192

// Scratch (static device globals — no runtime allocation allowed)
__device__ float g_qk[(size_t)MTOT * 512];   // per row: [0,256)=q heads, [256,512)=k heads
__device__ float g_v [(size_t)MTOT * DIM];
__device__ float g_ctx[(size_t)MTOT * DIM];

// ---------------------------------------------------------------------------
// SGEMM: C[M, NC] = A[M, 768] @ W[NC, 768]^T (+ bias). fp32 (unchanged).
// ---------------------------------------------------------------------------
template<int NC, bool BIAS>
__global__ void __launch_bounds__(256) sgemm_nt_k(const float* __restrict__ A,
                                                  const float* __restrict__ W,
                                                  const float* __restrict__ bias,
                                                  float* __restrict__ C)
{
    __shared__ float As[8][128];
    __shared__ float Ws[8][128];

    const int m0  = blockIdx.y * 128;
    const int n0  = blockIdx.x * 128;
    const int tid = threadIdx.x;
    const int ty  = tid >> 4;
    const int tx  = tid & 15;
    const int lr  = tid >> 1;
    const int lk  = (tid & 1) * 4;

    const float* Ap = A + (size_t)(m0 + lr) * DIM + lk;
    const float* Wp = W + (size_t)(n0 + lr) * DIM + lk;

    float acc[8][8];
#pragma unroll
    for (int r = 0; r < 8; r++)
#pragma unroll
        for (int c = 0; c < 8; c++) acc[r][c] = 0.f;

    for (int k0 = 0; k0 < DIM; k0 += 8) {
        float4 av = *(const float4*)(Ap + k0);
        float4 wv = *(const float4*)(Wp + k0);
        __syncthreads();
        As[lk + 0][lr] = av.x; As[lk + 1][lr] = av.y;
        As[lk + 2][lr] = av.z; As[lk + 3][lr] = av.w;
        Ws[lk + 0][lr] = wv.x; Ws[lk + 1][lr] = wv.y;
        Ws[lk + 2][lr] = wv.z; Ws[lk + 3][lr] = wv.w;
        __syncthreads();
#pragma unroll
        for (int kk = 0; kk < 8; kk++) {
            float a[8], w[8];
            *(float4*)(a)     = *(const float4*)&As[kk][ty * 4];
            *(float4*)(a + 4) = *(const float4*)&As[kk][64 + ty * 4];
            *(float4*)(w)     = *(const float4*)&Ws[kk][tx * 4];
            *(float4*)(w + 4) = *(const float4*)&Ws[kk][64 + tx * 4];
#pragma unroll
            for (int r = 0; r < 8; r++)
#pragma unroll
                for (int c = 0; c < 8; c++)
                    acc[r][c] += a[r] * w[c];
        }
    }

#pragma unroll
    for (int r = 0; r < 8; r++) {
        const int row = m0 + ((r < 4) ? (ty * 4 + r) : (64 + ty * 4 + r - 4));
#pragma unroll
        for (int cg = 0; cg < 2; cg++) {
            const int col = n0 + ((cg == 0) ? (tx * 4) : (64 + tx * 4));
            float4 o;
            o.x = acc[r][cg * 4 + 0]; o.y = acc[r][cg * 4 + 1];
            o.z = acc[r][cg * 4 + 2]; o.w = acc[r][cg * 4 + 3];
            if (BIAS) {
                const float4 bv = *(const float4*)&bias[col];
                o.x += bv.x; o.y += bv.y; o.z += bv.z; o.w += bv.w;
            }
            *(float4*)&C[(size_t)row * NC + col] = o;
        }
    }
}

// ---------------------------------------------------------------------------
// TF32 tensor-core flash attention.
// CTA: 64 i-rows for one (b,h). 8 warps: warp = (mstrip = w>>1, nhalf = w&1)
// covering rows [16*mstrip,+16) x cols [32*nhalf,+32) of the 64x64 S tile.
// mma.sync.m16n8k8 TF32; smem holds TF32 bit patterns (cvt.rna at fill time).
// ---------------------------------------------------------------------------
#define QS_STR 260   // == 4 (mod 32): frag loads bank = 4*row + q -> conflict-free
#define VS_STR 72    // == 8 (mod 32): V B-frag loads conflict-free
#define PS_STR 68    // AV A-frag loads conflict-free

__device__ __forceinline__ uint32_t f2tf(float x) {
    uint32_t r;
    asm("cvt.rna.tf32.f32 %0, %1;" : "=r"(r) : "f"(x));
    return r;
}

__device__ __forceinline__ void mma_tf32(float* d, const uint32_t* a, const uint32_t* b) {
    asm volatile(
        "mma.sync.aligned.m16n8k8.row.col.f32.tf32.tf32.f32 "
        "{%0,%1,%2,%3}, {%4,%5,%6,%7}, {%8,%9}, {%0,%1,%2,%3};"
        : "+f"(d[0]), "+f"(d[1]), "+f"(d[2]), "+f"(d[3])
        : "r"(a[0]), "r"(a[1]), "r"(a[2]), "r"(a[3]), "r"(b[0]), "r"(b[1]));
}

__global__ void __launch_bounds__(256) fish_attn_tc(const float* __restrict__ mixl,
                                                    float* __restrict__ ctx)
{
    extern __shared__ float sm[];
    float* Qs   = sm;                       // [64][QS_STR] tf32 bits
    float* Ks   = Qs + 64 * QS_STR;         // [64][QS_STR] tf32 bits
    float* Vs   = Ks + 64 * QS_STR;         // [64][VS_STR] tf32 bits
    float* Ps   = Vs + 64 * VS_STR;         // [64][PS_STR] tf32 bits
    float* sMax = Ps + 64 * PS_STR;         // [64][2]
    float* sSum = sMax + 128;               // [64][2]

    const int i0   = blockIdx.x * 64;
    const int h    = blockIdx.y;
    const int b    = blockIdx.z;
    const int tid  = threadIdx.x;
    const int lane = tid & 31;
    const int warp = tid >> 5;
    const int mstrip = warp >> 1;           // 0..3
    const int nhalf  = warp & 1;            // 0..1
    const int qd = lane >> 2;               // 0..7
    const int qq = lane & 3;                // 0..3

    const int row0 = 16 * mstrip + qd;      // S/O row owned by (this thread, c0/c1)
    const int row1 = row0 + 8;              // (c2/c3)

    // mix = softmax(mix_logits[h,:]) * HEAD_DIM^-0.5
    float ml0 = mixl[h * KG + 0], ml1 = mixl[h * KG + 1];
    float ml2 = mixl[h * KG + 2], ml3 = mixl[h * KG + 3];
    float mm = fmaxf(fmaxf(ml0, ml1), fmaxf(ml2, ml3));
    float e0 = expf(ml0 - mm), e1 = expf(ml1 - mm);
    float e2 = expf(ml2 - mm), e3 = expf(ml3 - mm);
    float inv_es = 0.125f / (e0 + e1 + e2 + e3);
    float mixw[KG] = {e0 * inv_es, e1 * inv_es, e2 * inv_es, e3 * inv_es};

    // Q' tile: load, scale, cvt->tf32 (once per CTA)
    {
        const int c = (tid & 63) * 4;
        const float s = mixw[c >> 6];
        for (int i = tid >> 6; i < 64; i += 4) {
            float4 q = *(const float4*)&g_qk[((size_t)(b * SEQ + i0 + i)) * 512 + c];
            uint32_t* dst = (uint32_t*)&Qs[i * QS_STR + c];
            dst[0] = f2tf(q.x * s); dst[1] = f2tf(q.y * s);
            dst[2] = f2tf(q.z * s); dst[3] = f2tf(q.w * s);
        }
    }

    float O[4][4];
#pragma unroll
    for (int nt = 0; nt < 4; nt++)
#pragma unroll
        for (int c = 0; c < 4; c++) O[nt][c] = 0.f;
    float m_0 = -INFINITY, m_1 = -INFINITY, l_0 = 0.f, l_1 = 0.f;

    const uint32_t* Qsu = (const uint32_t*)Qs;
    const uint32_t* Ksu = (const uint32_t*)Ks;
    const uint32_t* Psu = (const uint32_t*)Ps;
    const uint32_t* Vsu = (const uint32_t*)Vs;
    const uint32_t* qa0 = Qsu + row0 * QS_STR + qq;
    const uint32_t* qa1 = Qsu + row1 * QS_STR + qq;
    const uint32_t* pa0 = Psu + row0 * PS_STR + qq;
    const uint32_t* pa1 = Psu + row1 * PS_STR + qq;

    for (int j0 = 0; j0 < SEQ; j0 += 64) {
        __syncthreads();   // prior iter's smem reads complete (also covers Q stores, iter 0)
        // K tile: load + cvt
        {
            const int c = (tid & 63) * 4;
            for (int j = tid >> 6; j < 64; j += 4) {
                float4 k4 = *(const float4*)&g_qk[((size_t)(b * SEQ + j0 + j)) * 512 + 256 + c];
                uint32_t* dst = (uint32_t*)&Ks[j * QS_STR + c];
                dst[0] = f2tf(k4.x); dst[1] = f2tf(k4.y);
                dst[2] = f2tf(k4.z); dst[3] = f2tf(k4.w);
            }
        }
        // V tile (head h slice): load + cvt
        {
            const int d = (tid & 15) * 4;
            for (int j = tid >> 4; j < 64; j += 16) {
                float4 v4 = *(const float4*)&g_v[((size_t)(b * SEQ + j0 + j)) * DIM + h * HD + d];
                uint32_t* dst = (uint32_t*)&Vs[j * VS_STR + d];
                dst[0] = f2tf(v4.x); dst[1] = f2tf(v4.y);
                dst[2] = f2tf(v4.z); dst[3] = f2tf(v4.w);
            }
        }
        __syncthreads();

        // ---- S = Q' K^T (warp: 16 x 32) ----
        float S[4][4];
#pragma unroll
        for (int nt = 0; nt < 4; nt++)
#pragma unroll
            for (int c = 0; c < 4; c++) S[nt][c] = 0.f;

#pragma unroll 8
        for (int k0 = 0; k0 < QKD; k0 += 8) {
            uint32_t a[4];
            a[0] = qa0[k0]; a[1] = qa1[k0];
            a[2] = qa0[k0 + 4]; a[3] = qa1[k0 + 4];
#pragma unroll
            for (int nt = 0; nt < 4; nt++) {
                const int jc = 32 * nhalf + nt * 8 + qd;
                uint32_t bf[2];
                bf[0] = Ksu[jc * QS_STR + k0 + qq];
                bf[1] = Ksu[jc * QS_STR + k0 + qq + 4];
                mma_tf32(S[nt], a, bf);
            }
        }

        // ---- online softmax ----
        // strip max (this warp's 32 cols) per row
        float mx0 = fmaxf(S[0][0], S[0][1]), mx1 = fmaxf(S[0][2], S[0][3]);
#pragma unroll
        for (int nt = 1; nt < 4; nt++) {
            mx0 = fmaxf(mx0, fmaxf(S[nt][0], S[nt][1]));
            mx1 = fmaxf(mx1, fmaxf(S[nt][2], S[nt][3]));
        }
        mx0 = fmaxf(mx0, __shfl_xor_sync(0xffffffffu, mx0, 1));
        mx0 = fmaxf(mx0, __shfl_xor_sync(0xffffffffu, mx0, 2));
        mx1 = fmaxf(mx1, __shfl_xor_sync(0xffffffffu, mx1, 1));
        mx1 = fmaxf(mx1, __shfl_xor_sync(0xffffffffu, mx1, 2));
        if (qq == 0) {
            sMax[row0 * 2 + nhalf] = mx0;
            sMax[row1 * 2 + nhalf] = mx1;
        }
        __syncthreads();
        const float tm0 = fmaxf(sMax[row0 * 2], sMax[row0 * 2 + 1]);
        const float tm1 = fmaxf(sMax[row1 * 2], sMax[row1 * 2 + 1]);
        const float mn0 = fmaxf(m_0, tm0), mn1 = fmaxf(m_1, tm1);
        const float corr0 = __expf(m_0 - mn0), corr1 = __expf(m_1 - mn1);
        m_0 = mn0; m_1 = mn1;

        float rs0 = 0.f, rs1 = 0.f;
#pragma unroll
        for (int nt = 0; nt < 4; nt++) {
            const float p0 = __expf(S[nt][0] - mn0);
            const float p1 = __expf(S[nt][1] - mn0);
            const float p2 = __expf(S[nt][2] - mn1);
            const float p3 = __expf(S[nt][3] - mn1);
            rs0 += p0 + p1; rs1 += p2 + p3;
            const int col = 32 * nhalf + nt * 8 + 2 * qq;
            uint32_t* d0 = (uint32_t*)&Ps[row0 * PS_STR + col];
            uint32_t* d1 = (uint32_t*)&Ps[row1 * PS_STR + col];
            d0[0] = f2tf(p0); d0[1] = f2tf(p1);
            d1[0] = f2tf(p2); d1[1] = f2tf(p3);
            O[nt][0] *= corr0; O[nt][1] *= corr0;
            O[nt][2] *= corr1; O[nt][3] *= corr1;
        }
        rs0 += __shfl_xor_sync(0xffffffffu, rs0, 1);
        rs0 += __shfl_xor_sync(0xffffffffu, rs0, 2);
        rs1 += __shfl_xor_sync(0xffffffffu, rs1, 1);
        rs1 += __shfl_xor_sync(0xffffffffu, rs1, 2);
        if (qq == 0) {
            sSum[row0 * 2 + nhalf] = rs0;
            sSum[row1 * 2 + nhalf] = rs1;
        }
        __syncthreads();
        l_0 = l_0 * corr0 + sSum[row0 * 2] + sSum[row0 * 2 + 1];
        l_1 = l_1 * corr1 + sSum[row1 * 2] + sSum[row1 * 2 + 1];

        // ---- O += P V (warp: 16 x 32 over d) ----
#pragma unroll
        for (int k0 = 0; k0 < 64; k0 += 8) {
            uint32_t a[4];
            a[0] = pa0[k0]; a[1] = pa1[k0];
            a[2] = pa0[k0 + 4]; a[3] = pa1[k0 + 4];
#pragma unroll
            for (int nt = 0; nt < 4; nt++) {
                const int d = 32 * nhalf + nt * 8 + qd;
                uint32_t bf[2];
                bf[0] = Vsu[(k0 + qq) * VS_STR + d];
                bf[1] = Vsu[(k0 + qq + 4) * VS_STR + d];
                mma_tf32(O[nt], a, bf);
            }
        }
    }

    // Epilogue: normalize, write ctx (B,N,768)
    const float inv0 = 1.f / l_0, inv1 = 1.f / l_1;
    const size_t r0off = ((size_t)(b * SEQ + i0 + row0)) * DIM + h * HD;
    const size_t r1off = ((size_t)(b * SEQ + i0 + row1)) * DIM + h * HD;
#pragma unroll
    for (int nt = 0; nt < 4; nt++) {
        const int col = 32 * nhalf + nt * 8 + 2 * qq;
        float2 o0; o0.x = O[nt][0] * inv0; o0.y = O[nt][1] * inv0;
        float2 o1; o1.x = O[nt][2] * inv1; o1.y = O[nt][3] * inv1;
        *(float2*)&ctx[r0off + col] = o0;
        *(float2*)&ctx[r1off + col] = o1;
    }
}

// ---------------------------------------------------------------------------
// Launch
// ---------------------------------------------------------------------------
extern "C" void kernel_launch(void* const* d_in, const int* in_sizes, int n_in,
                              void* d_out, int out_size)
{
    const float* x      = (const float*)d_in[0];
    const float* w_qkv  = (const float*)d_in[1];
    const float* mixl   = (const float*)d_in[2];
    const float* w_v    = (const float*)d_in[3];
    const float* w_proj = (const float*)d_in[4];
    const float* b_proj = (const float*)d_in[5];
    float* out = (float*)d_out;

    float *qk, *v, *ctx;
    cudaGetSymbolAddress((void**)&qk,  g_qk);
    cudaGetSymbolAddress((void**)&v,   g_v);
    cudaGetSymbolAddress((void**)&ctx, g_ctx);

    const int attn_smem = (64 * QS_STR * 2 + 64 * VS_STR + 64 * PS_STR + 256) * (int)sizeof(float);
    cudaFuncSetAttribute(fish_attn_tc, cudaFuncAttributeMaxDynamicSharedMemorySize, attn_smem);

    // 1) qk = x @ w_qkv[0:512]^T   (q and k global heads; v-slice unused by reference)
    sgemm_nt_k<512, false><<<dim3(4, 64), 256>>>(x, w_qkv, nullptr, qk);
    // 2) v = x @ w_v^T
    sgemm_nt_k<768, false><<<dim3(6, 64), 256>>>(x, w_v, nullptr, v);
    // 3) fused mix + attention (TF32 tensor cores)
    fish_attn_tc<<<dim3(SEQ / 64, NH, BB), 256, attn_smem>>>(mixl, ctx);
    // 4) out = ctx @ w_proj^T + b_proj
    sgemm_nt_k<768, true><<<dim3(6, 64), 256>>>(ctx, w_proj, b_proj, out);
}

// round 4
// speedup vs baseline: 2.5539x; 1.3321x over previous
#include <cuda_runtime.h>
#include <math.h>
#include <stdint.h>

// Problem constants
#define BB   8
#define SEQ  1024
#define DIM  768
#define NH   12
#define KG   4
#define HD   64
#define QKD  256          // KG*HD : effective QK head dim after mix-fold
#define MTOT (BB*SEQ)     // 8192

// Scratch (static device globals — no runtime allocation allowed)
__device__ float g_qk[(size_t)MTOT * 512];   // per row: [0,256)=q heads, [256,512)=k heads
__device__ float g_v [(size_t)MTOT * DIM];
__device__ float g_ctx[(size_t)MTOT * DIM];

// ---------------------------------------------------------------------------
// TF32 helpers
// ---------------------------------------------------------------------------
__device__ __forceinline__ uint32_t f2tf(float x) {
    uint32_t r;
    asm("cvt.rna.tf32.f32 %0, %1;" : "=r"(r) : "f"(x));
    return r;
}

__device__ __forceinline__ void mma_tf32(float* d, const uint32_t* a, const uint32_t* b) {
    asm volatile(
        "mma.sync.aligned.m16n8k8.row.col.f32.tf32.tf32.f32 "
        "{%0,%1,%2,%3}, {%4,%5,%6,%7}, {%8,%9}, {%0,%1,%2,%3};"
        : "+f"(d[0]), "+f"(d[1]), "+f"(d[2]), "+f"(d[3])
        : "r"(a[0]), "r"(a[1]), "r"(a[2]), "r"(a[3]), "r"(b[0]), "r"(b[1]));
}

// ---------------------------------------------------------------------------
// TF32 tensor-core GEMM: C[M, NC] = A[M, 768] @ W[NC, 768]^T (+ bias).
// 128x128 block tile, k-step 32. 8 warps (2 m x 4 n), warp tile 64x32.
// Smem stride 36 words (==4 mod 32) -> all fragment loads bank-conflict-free.
// ---------------------------------------------------------------------------
#define GS_STR 36

template<int NC, bool BIAS>
__global__ void __launch_bounds__(256) tf32_gemm_nt(const float* __restrict__ A,
                                                    const float* __restrict__ W,
                                                    const float* __restrict__ bias,
                                                    float* __restrict__ C)
{
    __shared__ uint32_t As[128 * GS_STR];
    __shared__ uint32_t Ws[128 * GS_STR];

    const int m0  = blockIdx.y * 128;
    const int n0  = blockIdx.x * 128;
    const int tid = threadIdx.x;
    const int lane = tid & 31;
    const int warp = tid >> 5;
    const int warp_m = warp >> 2;        // 0..1
    const int warp_n = warp & 3;         // 0..3
    const int qd = lane >> 2;            // 0..7
    const int qq = lane & 3;             // 0..3

    const int lr = tid >> 1;             // 0..127 (row for global loads)
    const int lc = (tid & 1) * 16;       // 0 or 16 (col group, 4 float4s)

    const float* Ap = A + (size_t)(m0 + lr) * DIM + lc;
    const float* Wp = W + (size_t)(n0 + lr) * DIM + lc;
    uint32_t* Asd = &As[lr * GS_STR + lc];
    uint32_t* Wsd = &Ws[lr * GS_STR + lc];

    float acc[4][4][4];
#pragma unroll
    for (int mf = 0; mf < 4; mf++)
#pragma unroll
        for (int nf = 0; nf < 4; nf++)
#pragma unroll
            for (int c = 0; c < 4; c++) acc[mf][nf][c] = 0.f;

    for (int k0 = 0; k0 < DIM; k0 += 32) {
        float4 av[4], wv[4];
#pragma unroll
        for (int i = 0; i < 4; i++) {
            av[i] = *(const float4*)(Ap + k0 + i * 4);
            wv[i] = *(const float4*)(Wp + k0 + i * 4);
        }
        __syncthreads();   // previous iteration's fragment reads complete
#pragma unroll
        for (int i = 0; i < 4; i++) {
            uint4 at, wt;
            at.x = f2tf(av[i].x); at.y = f2tf(av[i].y);
            at.z = f2tf(av[i].z); at.w = f2tf(av[i].w);
            wt.x = f2tf(wv[i].x); wt.y = f2tf(wv[i].y);
            wt.z = f2tf(wv[i].z); wt.w = f2tf(wv[i].w);
            *(uint4*)(Asd + i * 4) = at;
            *(uint4*)(Wsd + i * 4) = wt;
        }
        __syncthreads();

#pragma unroll
        for (int kk = 0; kk < 32; kk += 8) {
            uint32_t a[4][4];
#pragma unroll
            for (int mf = 0; mf < 4; mf++) {
                const int base = warp_m * 64 + mf * 16 + qd;
                a[mf][0] = As[base * GS_STR + kk + qq];
                a[mf][1] = As[(base + 8) * GS_STR + kk + qq];
                a[mf][2] = As[base * GS_STR + kk + qq + 4];
                a[mf][3] = As[(base + 8) * GS_STR + kk + qq + 4];
            }
#pragma unroll
            for (int nf = 0; nf < 4; nf++) {
                const int col = warp_n * 32 + nf * 8 + qd;
                uint32_t bfr[2];
                bfr[0] = Ws[col * GS_STR + kk + qq];
                bfr[1] = Ws[col * GS_STR + kk + qq + 4];
#pragma unroll
                for (int mf = 0; mf < 4; mf++)
                    mma_tf32(acc[mf][nf], a[mf], bfr);
            }
        }
    }

    // Epilogue
#pragma unroll
    for (int mf = 0; mf < 4; mf++) {
        const int row0 = m0 + warp_m * 64 + mf * 16 + qd;
        const int row1 = row0 + 8;
#pragma unroll
        for (int nf = 0; nf < 4; nf++) {
            const int col = n0 + warp_n * 32 + nf * 8 + 2 * qq;
            float2 o0, o1;
            o0.x = acc[mf][nf][0]; o0.y = acc[mf][nf][1];
            o1.x = acc[mf][nf][2]; o1.y = acc[mf][nf][3];
            if (BIAS) {
                const float2 bv = *(const float2*)&bias[col];
                o0.x += bv.x; o0.y += bv.y;
                o1.x += bv.x; o1.y += bv.y;
            }
            *(float2*)&C[(size_t)row0 * NC + col] = o0;
            *(float2*)&C[(size_t)row1 * NC + col] = o1;
        }
    }
}

// ---------------------------------------------------------------------------
// TF32 tensor-core flash attention (unchanged from R2 WIN).
// ---------------------------------------------------------------------------
#define QS_STR 260
#define VS_STR 72
#define PS_STR 68

__global__ void __launch_bounds__(256) fish_attn_tc(const float* __restrict__ mixl,
                                                    float* __restrict__ ctx)
{
    extern __shared__ float sm[];
    float* Qs   = sm;                       // [64][QS_STR] tf32 bits
    float* Ks   = Qs + 64 * QS_STR;         // [64][QS_STR] tf32 bits
    float* Vs   = Ks + 64 * QS_STR;         // [64][VS_STR] tf32 bits
    float* Ps   = Vs + 64 * VS_STR;         // [64][PS_STR] tf32 bits
    float* sMax = Ps + 64 * PS_STR;         // [64][2]
    float* sSum = sMax + 128;               // [64][2]

    const int i0   = blockIdx.x * 64;
    const int h    = blockIdx.y;
    const int b    = blockIdx.z;
    const int tid  = threadIdx.x;
    const int lane = tid & 31;
    const int warp = tid >> 5;
    const int mstrip = warp >> 1;
    const int nhalf  = warp & 1;
    const int qd = lane >> 2;
    const int qq = lane & 3;

    const int row0 = 16 * mstrip + qd;
    const int row1 = row0 + 8;

    float ml0 = mixl[h * KG + 0], ml1 = mixl[h * KG + 1];
    float ml2 = mixl[h * KG + 2], ml3 = mixl[h * KG + 3];
    float mm = fmaxf(fmaxf(ml0, ml1), fmaxf(ml2, ml3));
    float e0 = expf(ml0 - mm), e1 = expf(ml1 - mm);
    float e2 = expf(ml2 - mm), e3 = expf(ml3 - mm);
    float inv_es = 0.125f / (e0 + e1 + e2 + e3);
    float mixw[KG] = {e0 * inv_es, e1 * inv_es, e2 * inv_es, e3 * inv_es};

    {
        const int c = (tid & 63) * 4;
        const float s = mixw[c >> 6];
        for (int i = tid >> 6; i < 64; i += 4) {
            float4 q = *(const float4*)&g_qk[((size_t)(b * SEQ + i0 + i)) * 512 + c];
            uint32_t* dst = (uint32_t*)&Qs[i * QS_STR + c];
            dst[0] = f2tf(q.x * s); dst[1] = f2tf(q.y * s);
            dst[2] = f2tf(q.z * s); dst[3] = f2tf(q.w * s);
        }
    }

    float O[4][4];
#pragma unroll
    for (int nt = 0; nt < 4; nt++)
#pragma unroll
        for (int c = 0; c < 4; c++) O[nt][c] = 0.f;
    float m_0 = -INFINITY, m_1 = -INFINITY, l_0 = 0.f, l_1 = 0.f;

    const uint32_t* Qsu = (const uint32_t*)Qs;
    const uint32_t* Ksu = (const uint32_t*)Ks;
    const uint32_t* Psu = (const uint32_t*)Ps;
    const uint32_t* Vsu = (const uint32_t*)Vs;
    const uint32_t* qa0 = Qsu + row0 * QS_STR + qq;
    const uint32_t* qa1 = Qsu + row1 * QS_STR + qq;
    const uint32_t* pa0 = Psu + row0 * PS_STR + qq;
    const uint32_t* pa1 = Psu + row1 * PS_STR + qq;

    for (int j0 = 0; j0 < SEQ; j0 += 64) {
        __syncthreads();
        {
            const int c = (tid & 63) * 4;
            for (int j = tid >> 6; j < 64; j += 4) {
                float4 k4 = *(const float4*)&g_qk[((size_t)(b * SEQ + j0 + j)) * 512 + 256 + c];
                uint32_t* dst = (uint32_t*)&Ks[j * QS_STR + c];
                dst[0] = f2tf(k4.x); dst[1] = f2tf(k4.y);
                dst[2] = f2tf(k4.z); dst[3] = f2tf(k4.w);
            }
        }
        {
            const int d = (tid & 15) * 4;
            for (int j = tid >> 4; j < 64; j += 16) {
                float4 v4 = *(const float4*)&g_v[((size_t)(b * SEQ + j0 + j)) * DIM + h * HD + d];
                uint32_t* dst = (uint32_t*)&Vs[j * VS_STR + d];
                dst[0] = f2tf(v4.x); dst[1] = f2tf(v4.y);
                dst[2] = f2tf(v4.z); dst[3] = f2tf(v4.w);
            }
        }
        __syncthreads();

        float S[4][4];
#pragma unroll
        for (int nt = 0; nt < 4; nt++)
#pragma unroll
            for (int c = 0; c < 4; c++) S[nt][c] = 0.f;

#pragma unroll 8
        for (int k0 = 0; k0 < QKD; k0 += 8) {
            uint32_t a[4];
            a[0] = qa0[k0]; a[1] = qa1[k0];
            a[2] = qa0[k0 + 4]; a[3] = qa1[k0 + 4];
#pragma unroll
            for (int nt = 0; nt < 4; nt++) {
                const int jc = 32 * nhalf + nt * 8 + qd;
                uint32_t bf[2];
                bf[0] = Ksu[jc * QS_STR + k0 + qq];
                bf[1] = Ksu[jc * QS_STR + k0 + qq + 4];
                mma_tf32(S[nt], a, bf);
            }
        }

        float mx0 = fmaxf(S[0][0], S[0][1]), mx1 = fmaxf(S[0][2], S[0][3]);
#pragma unroll
        for (int nt = 1; nt < 4; nt++) {
            mx0 = fmaxf(mx0, fmaxf(S[nt][0], S[nt][1]));
            mx1 = fmaxf(mx1, fmaxf(S[nt][2], S[nt][3]));
        }
        mx0 = fmaxf(mx0, __shfl_xor_sync(0xffffffffu, mx0, 1));
        mx0 = fmaxf(mx0, __shfl_xor_sync(0xffffffffu, mx0, 2));
        mx1 = fmaxf(mx1, __shfl_xor_sync(0xffffffffu, mx1, 1));
        mx1 = fmaxf(mx1, __shfl_xor_sync(0xffffffffu, mx1, 2));
        if (qq == 0) {
            sMax[row0 * 2 + nhalf] = mx0;
            sMax[row1 * 2 + nhalf] = mx1;
        }
        __syncthreads();
        const float tm0 = fmaxf(sMax[row0 * 2], sMax[row0 * 2 + 1]);
        const float tm1 = fmaxf(sMax[row1 * 2], sMax[row1 * 2 + 1]);
        const float mn0 = fmaxf(m_0, tm0), mn1 = fmaxf(m_1, tm1);
        const float corr0 = __expf(m_0 - mn0), corr1 = __expf(m_1 - mn1);
        m_0 = mn0; m_1 = mn1;

        float rs0 = 0.f, rs1 = 0.f;
#pragma unroll
        for (int nt = 0; nt < 4; nt++) {
            const float p0 = __expf(S[nt][0] - mn0);
            const float p1 = __expf(S[nt][1] - mn0);
            const float p2 = __expf(S[nt][2] - mn1);
            const float p3 = __expf(S[nt][3] - mn1);
            rs0 += p0 + p1; rs1 += p2 + p3;
            const int col = 32 * nhalf + nt * 8 + 2 * qq;
            uint32_t* d0 = (uint32_t*)&Ps[row0 * PS_STR + col];
            uint32_t* d1 = (uint32_t*)&Ps[row1 * PS_STR + col];
            d0[0] = f2tf(p0); d0[1] = f2tf(p1);
            d1[0] = f2tf(p2); d1[1] = f2tf(p3);
            O[nt][0] *= corr0; O[nt][1] *= corr0;
            O[nt][2] *= corr1; O[nt][3] *= corr1;
        }
        rs0 += __shfl_xor_sync(0xffffffffu, rs0, 1);
        rs0 += __shfl_xor_sync(0xffffffffu, rs0, 2);
        rs1 += __shfl_xor_sync(0xffffffffu, rs1, 1);
        rs1 += __shfl_xor_sync(0xffffffffu, rs1, 2);
        if (qq == 0) {
            sSum[row0 * 2 + nhalf] = rs0;
            sSum[row1 * 2 + nhalf] = rs1;
        }
        __syncthreads();
        l_0 = l_0 * corr0 + sSum[row0 * 2] + sSum[row0 * 2 + 1];
        l_1 = l_1 * corr1 + sSum[row1 * 2] + sSum[row1 * 2 + 1];

#pragma unroll
        for (int k0 = 0; k0 < 64; k0 += 8) {
            uint32_t a[4];
            a[0] = pa0[k0]; a[1] = pa1[k0];
            a[2] = pa0[k0 + 4]; a[3] = pa1[k0 + 4];
#pragma unroll
            for (int nt = 0; nt < 4; nt++) {
                const int d = 32 * nhalf + nt * 8 + qd;
                uint32_t bf[2];
                bf[0] = Vsu[(k0 + qq) * VS_STR + d];
                bf[1] = Vsu[(k0 + qq + 4) * VS_STR + d];
                mma_tf32(O[nt], a, bf);
            }
        }
    }

    const float inv0 = 1.f / l_0, inv1 = 1.f / l_1;
    const size_t r0off = ((size_t)(b * SEQ + i0 + row0)) * DIM + h * HD;
    const size_t r1off = ((size_t)(b * SEQ + i0 + row1)) * DIM + h * HD;
#pragma unroll
    for (int nt = 0; nt < 4; nt++) {
        const int col = 32 * nhalf + nt * 8 + 2 * qq;
        float2 o0; o0.x = O[nt][0] * inv0; o0.y = O[nt][1] * inv0;
        float2 o1; o1.x = O[nt][2] * inv1; o1.y = O[nt][3] * inv1;
        *(float2*)&ctx[r0off + col] = o0;
        *(float2*)&ctx[r1off + col] = o1;
    }
}

// ---------------------------------------------------------------------------
// Launch
// ---------------------------------------------------------------------------
extern "C" void kernel_launch(void* const* d_in, const int* in_sizes, int n_in,
                              void* d_out, int out_size)
{
    const float* x      = (const float*)d_in[0];
    const float* w_qkv  = (const float*)d_in[1];
    const float* mixl   = (const float*)d_in[2];
    const float* w_v    = (const float*)d_in[3];
    const float* w_proj = (const float*)d_in[4];
    const float* b_proj = (const float*)d_in[5];
    float* out = (float*)d_out;

    float *qk, *v, *ctx;
    cudaGetSymbolAddress((void**)&qk,  g_qk);
    cudaGetSymbolAddress((void**)&v,   g_v);
    cudaGetSymbolAddress((void**)&ctx, g_ctx);

    const int attn_smem = (64 * QS_STR * 2 + 64 * VS_STR + 64 * PS_STR + 256) * (int)sizeof(float);
    cudaFuncSetAttribute(fish_attn_tc, cudaFuncAttributeMaxDynamicSharedMemorySize, attn_smem);

    // 1) qk = x @ w_qkv[0:512]^T   (q and k global heads; v-slice unused by reference)
    tf32_gemm_nt<512, false><<<dim3(4, 64), 256>>>(x, w_qkv, nullptr, qk);
    // 2) v = x @ w_v^T
    tf32_gemm_nt<768, false><<<dim3(6, 64), 256>>>(x, w_v, nullptr, v);
    // 3) fused mix + attention (TF32 tensor cores)
    fish_attn_tc<<<dim3(SEQ / 64, NH, BB), 256, attn_smem>>>(mixl, ctx);
    // 4) out = ctx @ w_proj^T + b_proj
    tf32_gemm_nt<768, true><<<dim3(6, 64), 256>>>(ctx, w_proj, b_proj, out);
}

// round 5
// speedup vs baseline: 3.2588x; 1.2760x over previous
#include <cuda_runtime.h>
#include <math.h>
#include <stdint.h>

// Problem constants
#define BB   8
#define SEQ  1024
#define DIM  768
#define NH   12
#define KG   4
#define HD   64
#define QKD  256          // KG*HD : effective QK head dim after mix-fold
#define MTOT (BB*SEQ)     // 8192

// Scratch (static device globals — no runtime allocation allowed)
// g_qk / g_v hold TF32 bit patterns (converted in GEMM epilogue).
__device__ float g_qk[(size_t)MTOT * 512];   // per row: [0,256)=q heads, [256,512)=k heads
__device__ float g_v [(size_t)MTOT * DIM];
__device__ float g_ctx[(size_t)MTOT * DIM];

// ---------------------------------------------------------------------------
// TF32 / cp.async helpers
// ---------------------------------------------------------------------------
__device__ __forceinline__ uint32_t f2tf(float x) {
    uint32_t r;
    asm("cvt.rna.tf32.f32 %0, %1;" : "=r"(r) : "f"(x));
    return r;
}

__device__ __forceinline__ void mma_tf32(float* d, const uint32_t* a, const uint32_t* b) {
    asm volatile(
        "mma.sync.aligned.m16n8k8.row.col.f32.tf32.tf32.f32 "
        "{%0,%1,%2,%3}, {%4,%5,%6,%7}, {%8,%9}, {%0,%1,%2,%3};"
        : "+f"(d[0]), "+f"(d[1]), "+f"(d[2]), "+f"(d[3])
        : "r"(a[0]), "r"(a[1]), "r"(a[2]), "r"(a[3]), "r"(b[0]), "r"(b[1]));
}

__device__ __forceinline__ void cp16(uint32_t smem_dst, const void* gsrc) {
    asm volatile("cp.async.cg.shared.global [%0], [%1], 16;"
                 :: "r"(smem_dst), "l"(gsrc));
}
__device__ __forceinline__ void cp_commit() {
    asm volatile("cp.async.commit_group;");
}
__device__ __forceinline__ void cp_wait_all() {
    asm volatile("cp.async.wait_group 0;");
}

// ---------------------------------------------------------------------------
// TF32 tensor-core GEMM: C[M, NC] = A[M, 768] @ W[NC, 768]^T (+ bias).
// Software-pipelined: next k-block's global loads issued before the MMA block.
// ---------------------------------------------------------------------------
#define GS_STR 36

template<int NC, bool OUT_TF32, bool BIAS>
__global__ void __launch_bounds__(256, 2) tf32_gemm_nt(const float* __restrict__ A,
                                                       const float* __restrict__ W,
                                                       const float* __restrict__ bias,
                                                       float* __restrict__ C)
{
    __shared__ uint32_t As[128 * GS_STR];
    __shared__ uint32_t Ws[128 * GS_STR];

    const int m0  = blockIdx.y * 128;
    const int n0  = blockIdx.x * 128;
    const int tid = threadIdx.x;
    const int lane = tid & 31;
    const int warp = tid >> 5;
    const int warp_m = warp >> 2;        // 0..1
    const int warp_n = warp & 3;         // 0..3
    const int qd = lane >> 2;            // 0..7
    const int qq = lane & 3;             // 0..3

    const int lr = tid >> 1;             // 0..127 (row for global loads)
    const int lc = (tid & 1) * 16;       // 0 or 16

    const float* Ap = A + (size_t)(m0 + lr) * DIM + lc;
    const float* Wp = W + (size_t)(n0 + lr) * DIM + lc;
    uint32_t* Asd = &As[lr * GS_STR + lc];
    uint32_t* Wsd = &Ws[lr * GS_STR + lc];

    float acc[4][4][4];
#pragma unroll
    for (int mf = 0; mf < 4; mf++)
#pragma unroll
        for (int nf = 0; nf < 4; nf++)
#pragma unroll
            for (int c = 0; c < 4; c++) acc[mf][nf][c] = 0.f;

    // Prologue: load k-block 0
    float4 av[4], wv[4];
#pragma unroll
    for (int i = 0; i < 4; i++) {
        av[i] = *(const float4*)(Ap + i * 4);
        wv[i] = *(const float4*)(Wp + i * 4);
    }

    for (int k0 = 0; k0 < DIM; k0 += 32) {
        __syncthreads();   // previous iteration's fragment reads complete
#pragma unroll
        for (int i = 0; i < 4; i++) {
            uint4 at, wt;
            at.x = f2tf(av[i].x); at.y = f2tf(av[i].y);
            at.z = f2tf(av[i].z); at.w = f2tf(av[i].w);
            wt.x = f2tf(wv[i].x); wt.y = f2tf(wv[i].y);
            wt.z = f2tf(wv[i].z); wt.w = f2tf(wv[i].w);
            *(uint4*)(Asd + i * 4) = at;
            *(uint4*)(Wsd + i * 4) = wt;
        }
        __syncthreads();

        // Prefetch next k-block (latency overlaps the MMA block below)
        if (k0 + 32 < DIM) {
#pragma unroll
            for (int i = 0; i < 4; i++) {
                av[i] = *(const float4*)(Ap + k0 + 32 + i * 4);
                wv[i] = *(const float4*)(Wp + k0 + 32 + i * 4);
            }
        }

#pragma unroll
        for (int kk = 0; kk < 32; kk += 8) {
            uint32_t a[4][4];
#pragma unroll
            for (int mf = 0; mf < 4; mf++) {
                const int base = warp_m * 64 + mf * 16 + qd;
                a[mf][0] = As[base * GS_STR + kk + qq];
                a[mf][1] = As[(base + 8) * GS_STR + kk + qq];
                a[mf][2] = As[base * GS_STR + kk + qq + 4];
                a[mf][3] = As[(base + 8) * GS_STR + kk + qq + 4];
            }
#pragma unroll
            for (int nf = 0; nf < 4; nf++) {
                const int col = warp_n * 32 + nf * 8 + qd;
                uint32_t bfr[2];
                bfr[0] = Ws[col * GS_STR + kk + qq];
                bfr[1] = Ws[col * GS_STR + kk + qq + 4];
#pragma unroll
                for (int mf = 0; mf < 4; mf++)
                    mma_tf32(acc[mf][nf], a[mf], bfr);
            }
        }
    }

    // Epilogue
#pragma unroll
    for (int mf = 0; mf < 4; mf++) {
        const int row0 = m0 + warp_m * 64 + mf * 16 + qd;
        const int row1 = row0 + 8;
#pragma unroll
        for (int nf = 0; nf < 4; nf++) {
            const int col = n0 + warp_n * 32 + nf * 8 + 2 * qq;
            float2 o0, o1;
            o0.x = acc[mf][nf][0]; o0.y = acc[mf][nf][1];
            o1.x = acc[mf][nf][2]; o1.y = acc[mf][nf][3];
            if (BIAS) {
                const float2 bv = *(const float2*)&bias[col];
                o0.x += bv.x; o0.y += bv.y;
                o1.x += bv.x; o1.y += bv.y;
            }
            if (OUT_TF32) {
                o0.x = __uint_as_float(f2tf(o0.x)); o0.y = __uint_as_float(f2tf(o0.y));
                o1.x = __uint_as_float(f2tf(o1.x)); o1.y = __uint_as_float(f2tf(o1.y));
            }
            *(float2*)&C[(size_t)row0 * NC + col] = o0;
            *(float2*)&C[(size_t)row1 * NC + col] = o1;
        }
    }
}

// ---------------------------------------------------------------------------
// TF32 tensor-core flash attention with cp.async K prefetch + V double buffer.
// Inputs g_qk/g_v already hold TF32 bit patterns.
// ---------------------------------------------------------------------------
#define QS_STR 260
#define VS_STR 72
#define PS_STR 68

__global__ void __launch_bounds__(256) fish_attn_tc(const float* __restrict__ mixl,
                                                    float* __restrict__ ctx)
{
    extern __shared__ float sm[];
    float* Qs   = sm;                        // [64][QS_STR] tf32 bits
    float* Ks   = Qs + 64 * QS_STR;          // [64][QS_STR] tf32 bits
    float* Vs0  = Ks + 64 * QS_STR;          // [2][64][VS_STR] tf32 bits
    float* Vs1  = Vs0 + 64 * VS_STR;
    float* Ps   = Vs1 + 64 * VS_STR;         // [64][PS_STR] tf32 bits
    float* sMax = Ps + 64 * PS_STR;          // [64][2]
    float* sSum = sMax + 128;                // [64][2]

    const int i0   = blockIdx.x * 64;
    const int h    = blockIdx.y;
    const int b    = blockIdx.z;
    const int tid  = threadIdx.x;
    const int lane = tid & 31;
    const int warp = tid >> 5;
    const int mstrip = warp >> 1;
    const int nhalf  = warp & 1;
    const int qd = lane >> 2;
    const int qq = lane & 3;

    const int row0 = 16 * mstrip + qd;
    const int row1 = row0 + 8;

    // Per-thread copy slots
    const int kc = (tid & 63) * 4;           // K: 16B chunk col
    const int kr = tid >> 6;                 // K: rows kr, kr+4, ... (16 rows)
    const int vd = (tid & 15) * 4;           // V: 16B chunk col
    const int vr = tid >> 4;                 // V: rows vr, vr+16, ... (4 rows)

    const uint32_t KsA  = (uint32_t)__cvta_generic_to_shared(Ks);
    const uint32_t VsA0 = (uint32_t)__cvta_generic_to_shared(Vs0);
    const uint32_t VsA1 = (uint32_t)__cvta_generic_to_shared(Vs1);

    // Prologue: async-copy K(0) and V(0)
#pragma unroll
    for (int i = 0; i < 16; i++) {
        const int j = kr + i * 4;
        cp16(KsA + (uint32_t)(j * QS_STR + kc) * 4,
             &g_qk[((size_t)(b * SEQ + 0 + j)) * 512 + 256 + kc]);
    }
#pragma unroll
    for (int i = 0; i < 4; i++) {
        const int j = vr + i * 16;
        cp16(VsA0 + (uint32_t)(j * VS_STR + vd) * 4,
             &g_v[((size_t)(b * SEQ + 0 + j)) * DIM + h * HD + vd]);
    }
    cp_commit();

    // mix = softmax(mix_logits[h,:]) * HEAD_DIM^-0.5
    float ml0 = mixl[h * KG + 0], ml1 = mixl[h * KG + 1];
    float ml2 = mixl[h * KG + 2], ml3 = mixl[h * KG + 3];
    float mm = fmaxf(fmaxf(ml0, ml1), fmaxf(ml2, ml3));
    float e0 = expf(ml0 - mm), e1 = expf(ml1 - mm);
    float e2 = expf(ml2 - mm), e3 = expf(ml3 - mm);
    float inv_es = 0.125f / (e0 + e1 + e2 + e3);
    float mixw[KG] = {e0 * inv_es, e1 * inv_es, e2 * inv_es, e3 * inv_es};

    // Q' tile: load tf32 bits, scale, re-round (once per CTA)
    {
        const float s = mixw[kc >> 6];
        for (int i = kr; i < 64; i += 4) {
            float4 q = *(const float4*)&g_qk[((size_t)(b * SEQ + i0 + i)) * 512 + kc];
            uint32_t* dst = (uint32_t*)&Qs[i * QS_STR + kc];
            dst[0] = f2tf(q.x * s); dst[1] = f2tf(q.y * s);
            dst[2] = f2tf(q.z * s); dst[3] = f2tf(q.w * s);
        }
    }

    float O[4][4];
#pragma unroll
    for (int nt = 0; nt < 4; nt++)
#pragma unroll
        for (int c = 0; c < 4; c++) O[nt][c] = 0.f;
    float m_0 = -INFINITY, m_1 = -INFINITY, l_0 = 0.f, l_1 = 0.f;

    const uint32_t* Qsu = (const uint32_t*)Qs;
    const uint32_t* Ksu = (const uint32_t*)Ks;
    const uint32_t* Psu = (const uint32_t*)Ps;
    const uint32_t* qa0 = Qsu + row0 * QS_STR + qq;
    const uint32_t* qa1 = Qsu + row1 * QS_STR + qq;
    const uint32_t* pa0 = Psu + row0 * PS_STR + qq;
    const uint32_t* pa1 = Psu + row1 * PS_STR + qq;

    for (int j0 = 0; j0 < SEQ; j0 += 64) {
        const int vbuf = (j0 >> 6) & 1;
        const uint32_t* Vsu = (const uint32_t*)(vbuf ? Vs1 : Vs0);
        const bool more = (j0 + 64 < SEQ);

        cp_wait_all();       // K(j), V(j) landed
        __syncthreads();     // visible to all; prior iter's smem reads done

        // Prefetch V(j+1) into the other buffer (overlaps everything below)
        if (more) {
            const uint32_t dstA = vbuf ? VsA0 : VsA1;
#pragma unroll
            for (int i = 0; i < 4; i++) {
                const int j = vr + i * 16;
                cp16(dstA + (uint32_t)(j * VS_STR + vd) * 4,
                     &g_v[((size_t)(b * SEQ + j0 + 64 + j)) * DIM + h * HD + vd]);
            }
            cp_commit();
        }

        // ---- S = Q' K^T ----
        float S[4][4];
#pragma unroll
        for (int nt = 0; nt < 4; nt++)
#pragma unroll
            for (int c = 0; c < 4; c++) S[nt][c] = 0.f;

#pragma unroll 8
        for (int k0 = 0; k0 < QKD; k0 += 8) {
            uint32_t a[4];
            a[0] = qa0[k0]; a[1] = qa1[k0];
            a[2] = qa0[k0 + 4]; a[3] = qa1[k0 + 4];
#pragma unroll
            for (int nt = 0; nt < 4; nt++) {
                const int jc = 32 * nhalf + nt * 8 + qd;
                uint32_t bf[2];
                bf[0] = Ksu[jc * QS_STR + k0 + qq];
                bf[1] = Ksu[jc * QS_STR + k0 + qq + 4];
                mma_tf32(S[nt], a, bf);
            }
        }

        // strip max + stats exchange
        float mx0 = fmaxf(S[0][0], S[0][1]), mx1 = fmaxf(S[0][2], S[0][3]);
#pragma unroll
        for (int nt = 1; nt < 4; nt++) {
            mx0 = fmaxf(mx0, fmaxf(S[nt][0], S[nt][1]));
            mx1 = fmaxf(mx1, fmaxf(S[nt][2], S[nt][3]));
        }
        mx0 = fmaxf(mx0, __shfl_xor_sync(0xffffffffu, mx0, 1));
        mx0 = fmaxf(mx0, __shfl_xor_sync(0xffffffffu, mx0, 2));
        mx1 = fmaxf(mx1, __shfl_xor_sync(0xffffffffu, mx1, 1));
        mx1 = fmaxf(mx1, __shfl_xor_sync(0xffffffffu, mx1, 2));
        if (qq == 0) {
            sMax[row0 * 2 + nhalf] = mx0;
            sMax[row1 * 2 + nhalf] = mx1;
        }
        __syncthreads();     // all warps done with Ks reads AND sMax written

        // Prefetch K(j+1) into Ks (overlaps softmax + AV)
        if (more) {
#pragma unroll
            for (int i = 0; i < 16; i++) {
                const int j = kr + i * 4;
                cp16(KsA + (uint32_t)(j * QS_STR + kc) * 4,
                     &g_qk[((size_t)(b * SEQ + j0 + 64 + j)) * 512 + 256 + kc]);
            }
            cp_commit();
        }

        const float tm0 = fmaxf(sMax[row0 * 2], sMax[row0 * 2 + 1]);
        const float tm1 = fmaxf(sMax[row1 * 2], sMax[row1 * 2 + 1]);
        const float mn0 = fmaxf(m_0, tm0), mn1 = fmaxf(m_1, tm1);
        const float corr0 = __expf(m_0 - mn0), corr1 = __expf(m_1 - mn1);
        m_0 = mn0; m_1 = mn1;

        float rs0 = 0.f, rs1 = 0.f;
#pragma unroll
        for (int nt = 0; nt < 4; nt++) {
            const float p0 = __expf(S[nt][0] - mn0);
            const float p1 = __expf(S[nt][1] - mn0);
            const float p2 = __expf(S[nt][2] - mn1);
            const float p3 = __expf(S[nt][3] - mn1);
            rs0 += p0 + p1; rs1 += p2 + p3;
            const int col = 32 * nhalf + nt * 8 + 2 * qq;
            uint2 w0, w1;
            w0.x = f2tf(p0); w0.y = f2tf(p1);
            w1.x = f2tf(p2); w1.y = f2tf(p3);
            *(uint2*)&Ps[row0 * PS_STR + col] = w0;
            *(uint2*)&Ps[row1 * PS_STR + col] = w1;
            O[nt][0] *= corr0; O[nt][1] *= corr0;
            O[nt][2] *= corr1; O[nt][3] *= corr1;
        }
        rs0 += __shfl_xor_sync(0xffffffffu, rs0, 1);
        rs0 += __shfl_xor_sync(0xffffffffu, rs0, 2);
        rs1 += __shfl_xor_sync(0xffffffffu, rs1, 1);
        rs1 += __shfl_xor_sync(0xffffffffu, rs1, 2);
        if (qq == 0) {
            sSum[row0 * 2 + nhalf] = rs0;
            sSum[row1 * 2 + nhalf] = rs1;
        }
        __syncthreads();     // Ps complete + sSum written
        l_0 = l_0 * corr0 + sSum[row0 * 2] + sSum[row0 * 2 + 1];
        l_1 = l_1 * corr1 + sSum[row1 * 2] + sSum[row1 * 2 + 1];

        // ---- O += P V ----
#pragma unroll
        for (int k0 = 0; k0 < 64; k0 += 8) {
            uint32_t a[4];
            a[0] = pa0[k0]; a[1] = pa1[k0];
            a[2] = pa0[k0 + 4]; a[3] = pa1[k0 + 4];
#pragma unroll
            for (int nt = 0; nt < 4; nt++) {
                const int d = 32 * nhalf + nt * 8 + qd;
                uint32_t bf[2];
                bf[0] = Vsu[(k0 + qq) * VS_STR + d];
                bf[1] = Vsu[(k0 + qq + 4) * VS_STR + d];
                mma_tf32(O[nt], a, bf);
            }
        }
    }

    // Epilogue: normalize, write ctx (B,N,768) fp32
    const float inv0 = 1.f / l_0, inv1 = 1.f / l_1;
    const size_t r0off = ((size_t)(b * SEQ + i0 + row0)) * DIM + h * HD;
    const size_t r1off = ((size_t)(b * SEQ + i0 + row1)) * DIM + h * HD;
#pragma unroll
    for (int nt = 0; nt < 4; nt++) {
        const int col = 32 * nhalf + nt * 8 + 2 * qq;
        float2 o0; o0.x = O[nt][0] * inv0; o0.y = O[nt][1] * inv0;
        float2 o1; o1.x = O[nt][2] * inv1; o1.y = O[nt][3] * inv1;
        *(float2*)&ctx[r0off + col] = o0;
        *(float2*)&ctx[r1off + col] = o1;
    }
}

// ---------------------------------------------------------------------------
// Launch
// ---------------------------------------------------------------------------
extern "C" void kernel_launch(void* const* d_in, const int* in_sizes, int n_in,
                              void* d_out, int out_size)
{
    const float* x      = (const float*)d_in[0];
    const float* w_qkv  = (const float*)d_in[1];
    const float* mixl   = (const float*)d_in[2];
    const float* w_v    = (const float*)d_in[3];
    const float* w_proj = (const float*)d_in[4];
    const float* b_proj = (const float*)d_in[5];
    float* out = (float*)d_out;

    float *qk, *v, *ctx;
    cudaGetSymbolAddress((void**)&qk,  g_qk);
    cudaGetSymbolAddress((void**)&v,   g_v);
    cudaGetSymbolAddress((void**)&ctx, g_ctx);

    const int attn_smem = (64 * QS_STR * 2 + 2 * 64 * VS_STR + 64 * PS_STR + 256) * (int)sizeof(float);
    cudaFuncSetAttribute(fish_attn_tc, cudaFuncAttributeMaxDynamicSharedMemorySize, attn_smem);

    // 1) qk = x @ w_qkv[0:512]^T  -> tf32 bits
    tf32_gemm_nt<512, true, false><<<dim3(4, 64), 256>>>(x, w_qkv, nullptr, qk);
    // 2) v = x @ w_v^T            -> tf32 bits
    tf32_gemm_nt<768, true, false><<<dim3(6, 64), 256>>>(x, w_v, nullptr, v);
    // 3) fused mix + attention (TF32 tensor cores, cp.async pipelined)
    fish_attn_tc<<<dim3(SEQ / 64, NH, BB), 256, attn_smem>>>(mixl, ctx);
    // 4) out = ctx @ w_proj^T + b_proj (fp32 out)
    tf32_gemm_nt<768, false, true><<<dim3(6, 64), 256>>>(ctx, w_proj, b_proj, out);
}

// round 6
// speedup vs baseline: 4.2762x; 1.3122x over previous
#include <cuda_runtime.h>
#include <math.h>
#include <stdint.h>

// Problem constants
#define BB   8
#define SEQ  1024
#define DIM  768
#define NH   12
#define KG   4
#define HD   64
#define MTOT (BB*SEQ)     // 8192

// Scratch (static device globals — no runtime allocation allowed)
// g_qk / g_v hold TF32 bit patterns (converted in GEMM epilogue).
__device__ float g_qk[(size_t)MTOT * 512];   // per row: [0,256)=q heads, [256,512)=k heads
__device__ float g_v [(size_t)MTOT * DIM];
__device__ float g_ctx[(size_t)MTOT * DIM];
__device__ float g_gl[(size_t)BB * KG * SEQ * SEQ];   // raw global logits q_k . k_k^T

// ---------------------------------------------------------------------------
// TF32 / cp.async helpers
// ---------------------------------------------------------------------------
__device__ __forceinline__ uint32_t f2tf(float x) {
    uint32_t r;
    asm("cvt.rna.tf32.f32 %0, %1;" : "=r"(r) : "f"(x));
    return r;
}

__device__ __forceinline__ void mma_tf32(float* d, const uint32_t* a, const uint32_t* b) {
    asm volatile(
        "mma.sync.aligned.m16n8k8.row.col.f32.tf32.tf32.f32 "
        "{%0,%1,%2,%3}, {%4,%5,%6,%7}, {%8,%9}, {%0,%1,%2,%3};"
        : "+f"(d[0]), "+f"(d[1]), "+f"(d[2]), "+f"(d[3])
        : "r"(a[0]), "r"(a[1]), "r"(a[2]), "r"(a[3]), "r"(b[0]), "r"(b[1]));
}

__device__ __forceinline__ void cp16(uint32_t smem_dst, const void* gsrc) {
    asm volatile("cp.async.cg.shared.global [%0], [%1], 16;"
                 :: "r"(smem_dst), "l"(gsrc));
}
__device__ __forceinline__ void cp_commit() {
    asm volatile("cp.async.commit_group;");
}
__device__ __forceinline__ void cp_wait_all() {
    asm volatile("cp.async.wait_group 0;");
}

// ---------------------------------------------------------------------------
// TF32 tensor-core GEMM: C[M, NC] = A[M, 768] @ W[NC, 768]^T (+ bias).
// ---------------------------------------------------------------------------
#define GS_STR 36

template<int NC, bool OUT_TF32, bool BIAS>
__global__ void __launch_bounds__(256, 2) tf32_gemm_nt(const float* __restrict__ A,
                                                       const float* __restrict__ W,
                                                       const float* __restrict__ bias,
                                                       float* __restrict__ C)
{
    __shared__ uint32_t As[128 * GS_STR];
    __shared__ uint32_t Ws[128 * GS_STR];

    const int m0  = blockIdx.y * 128;
    const int n0  = blockIdx.x * 128;
    const int tid = threadIdx.x;
    const int lane = tid & 31;
    const int warp = tid >> 5;
    const int warp_m = warp >> 2;
    const int warp_n = warp & 3;
    const int qd = lane >> 2;
    const int qq = lane & 3;

    const int lr = tid >> 1;
    const int lc = (tid & 1) * 16;

    const float* Ap = A + (size_t)(m0 + lr) * DIM + lc;
    const float* Wp = W + (size_t)(n0 + lr) * DIM + lc;
    uint32_t* Asd = &As[lr * GS_STR + lc];
    uint32_t* Wsd = &Ws[lr * GS_STR + lc];

    float acc[4][4][4];
#pragma unroll
    for (int mf = 0; mf < 4; mf++)
#pragma unroll
        for (int nf = 0; nf < 4; nf++)
#pragma unroll
            for (int c = 0; c < 4; c++) acc[mf][nf][c] = 0.f;

    float4 av[4], wv[4];
#pragma unroll
    for (int i = 0; i < 4; i++) {
        av[i] = *(const float4*)(Ap + i * 4);
        wv[i] = *(const float4*)(Wp + i * 4);
    }

    for (int k0 = 0; k0 < DIM; k0 += 32) {
        __syncthreads();
#pragma unroll
        for (int i = 0; i < 4; i++) {
            uint4 at, wt;
            at.x = f2tf(av[i].x); at.y = f2tf(av[i].y);
            at.z = f2tf(av[i].z); at.w = f2tf(av[i].w);
            wt.x = f2tf(wv[i].x); wt.y = f2tf(wv[i].y);
            wt.z = f2tf(wv[i].z); wt.w = f2tf(wv[i].w);
            *(uint4*)(Asd + i * 4) = at;
            *(uint4*)(Wsd + i * 4) = wt;
        }
        __syncthreads();

        if (k0 + 32 < DIM) {
#pragma unroll
            for (int i = 0; i < 4; i++) {
                av[i] = *(const float4*)(Ap + k0 + 32 + i * 4);
                wv[i] = *(const float4*)(Wp + k0 + 32 + i * 4);
            }
        }

#pragma unroll
        for (int kk = 0; kk < 32; kk += 8) {
            uint32_t a[4][4];
#pragma unroll
            for (int mf = 0; mf < 4; mf++) {
                const int base = warp_m * 64 + mf * 16 + qd;
                a[mf][0] = As[base * GS_STR + kk + qq];
                a[mf][1] = As[(base + 8) * GS_STR + kk + qq];
                a[mf][2] = As[base * GS_STR + kk + qq + 4];
                a[mf][3] = As[(base + 8) * GS_STR + kk + qq + 4];
            }
#pragma unroll
            for (int nf = 0; nf < 4; nf++) {
                const int col = warp_n * 32 + nf * 8 + qd;
                uint32_t bfr[2];
                bfr[0] = Ws[col * GS_STR + kk + qq];
                bfr[1] = Ws[col * GS_STR + kk + qq + 4];
#pragma unroll
                for (int mf = 0; mf < 4; mf++)
                    mma_tf32(acc[mf][nf], a[mf], bfr);
            }
        }
    }

#pragma unroll
    for (int mf = 0; mf < 4; mf++) {
        const int row0 = m0 + warp_m * 64 + mf * 16 + qd;
        const int row1 = row0 + 8;
#pragma unroll
        for (int nf = 0; nf < 4; nf++) {
            const int col = n0 + warp_n * 32 + nf * 8 + 2 * qq;
            float2 o0, o1;
            o0.x = acc[mf][nf][0]; o0.y = acc[mf][nf][1];
            o1.x = acc[mf][nf][2]; o1.y = acc[mf][nf][3];
            if (BIAS) {
                const float2 bv = *(const float2*)&bias[col];
                o0.x += bv.x; o0.y += bv.y;
                o1.x += bv.x; o1.y += bv.y;
            }
            if (OUT_TF32) {
                o0.x = __uint_as_float(f2tf(o0.x)); o0.y = __uint_as_float(f2tf(o0.y));
                o1.x = __uint_as_float(f2tf(o1.x)); o1.y = __uint_as_float(f2tf(o1.y));
            }
            *(float2*)&C[(size_t)row0 * NC + col] = o0;
            *(float2*)&C[(size_t)row1 * NC + col] = o1;
        }
    }
}

// ---------------------------------------------------------------------------
// Kernel A: global logits. For (b, kh): gl[i,j] = q_kh[i] . k_kh[j], K=64.
// Inputs in g_qk already tf32 bits (bit-copied to smem, no cvt needed).
// grid (8, 8, 32): x = j-tile, y = i-tile, z = b*4 + kh.
// ---------------------------------------------------------------------------
__global__ void __launch_bounds__(256, 2) gl_gemm(const float* __restrict__ QK,
                                                  float* __restrict__ GL)
{
    __shared__ uint32_t As[128 * GS_STR];
    __shared__ uint32_t Ws[128 * GS_STR];

    const int b  = blockIdx.z >> 2;
    const int kh = blockIdx.z & 3;
    const int m0 = blockIdx.y * 128;
    const int n0 = blockIdx.x * 128;
    const int tid = threadIdx.x;
    const int lane = tid & 31;
    const int warp = tid >> 5;
    const int warp_m = warp >> 2;
    const int warp_n = warp & 3;
    const int qd = lane >> 2;
    const int qq = lane & 3;

    const int lr = tid >> 1;
    const int lc = (tid & 1) * 16;

    const uint32_t* Ap = (const uint32_t*)QK + (size_t)(b * SEQ + m0 + lr) * 512 + kh * HD + lc;
    const uint32_t* Wp = (const uint32_t*)QK + (size_t)(b * SEQ + n0 + lr) * 512 + 256 + kh * HD + lc;
    uint32_t* Asd = &As[lr * GS_STR + lc];
    uint32_t* Wsd = &Ws[lr * GS_STR + lc];

    float acc[4][4][4];
#pragma unroll
    for (int mf = 0; mf < 4; mf++)
#pragma unroll
        for (int nf = 0; nf < 4; nf++)
#pragma unroll
            for (int c = 0; c < 4; c++) acc[mf][nf][c] = 0.f;

    uint4 av[4], wv[4];
#pragma unroll
    for (int i = 0; i < 4; i++) {
        av[i] = *(const uint4*)(Ap + i * 4);
        wv[i] = *(const uint4*)(Wp + i * 4);
    }

#pragma unroll
    for (int k0 = 0; k0 < HD; k0 += 32) {
        __syncthreads();
#pragma unroll
        for (int i = 0; i < 4; i++) {
            *(uint4*)(Asd + i * 4) = av[i];
            *(uint4*)(Wsd + i * 4) = wv[i];
        }
        __syncthreads();

        if (k0 + 32 < HD) {
#pragma unroll
            for (int i = 0; i < 4; i++) {
                av[i] = *(const uint4*)(Ap + k0 + 32 + i * 4);
                wv[i] = *(const uint4*)(Wp + k0 + 32 + i * 4);
            }
        }

#pragma unroll
        for (int kk = 0; kk < 32; kk += 8) {
            uint32_t a[4][4];
#pragma unroll
            for (int mf = 0; mf < 4; mf++) {
                const int base = warp_m * 64 + mf * 16 + qd;
                a[mf][0] = As[base * GS_STR + kk + qq];
                a[mf][1] = As[(base + 8) * GS_STR + kk + qq];
                a[mf][2] = As[base * GS_STR + kk + qq + 4];
                a[mf][3] = As[(base + 8) * GS_STR + kk + qq + 4];
            }
#pragma unroll
            for (int nf = 0; nf < 4; nf++) {
                const int col = warp_n * 32 + nf * 8 + qd;
                uint32_t bfr[2];
                bfr[0] = Ws[col * GS_STR + kk + qq];
                bfr[1] = Ws[col * GS_STR + kk + qq + 4];
#pragma unroll
                for (int mf = 0; mf < 4; mf++)
                    mma_tf32(acc[mf][nf], a[mf], bfr);
            }
        }
    }

    float* Cp = GL + (size_t)blockIdx.z * SEQ * SEQ;
#pragma unroll
    for (int mf = 0; mf < 4; mf++) {
        const int row0 = m0 + warp_m * 64 + mf * 16 + qd;
        const int row1 = row0 + 8;
#pragma unroll
        for (int nf = 0; nf < 4; nf++) {
            const int col = n0 + warp_n * 32 + nf * 8 + 2 * qq;
            float2 o0, o1;
            o0.x = acc[mf][nf][0]; o0.y = acc[mf][nf][1];
            o1.x = acc[mf][nf][2]; o1.y = acc[mf][nf][3];
            *(float2*)&Cp[(size_t)row0 * SEQ + col] = o0;
            *(float2*)&Cp[(size_t)row1 * SEQ + col] = o1;
        }
    }
}

// ---------------------------------------------------------------------------
// Kernel B: mix + softmax + AV. Streams Sg tiles (4 k-heads) via cp.async,
// forms S = sum_k mixw[k]*Sg_k in registers, online softmax, P.V on MMA.
// ---------------------------------------------------------------------------
#define SG_STR 68
#define VS_STR 72
#define PS_STR 68

__global__ void __launch_bounds__(256) fish_mix_attn(const float* __restrict__ mixl,
                                                     float* __restrict__ ctx)
{
    extern __shared__ float sm[];
    float* Sg   = sm;                         // [4][64][SG_STR]
    float* Vs0  = Sg + 4 * 64 * SG_STR;       // [2][64][VS_STR] tf32 bits
    float* Vs1  = Vs0 + 64 * VS_STR;
    float* Ps   = Vs1 + 64 * VS_STR;          // [64][PS_STR] tf32 bits
    float* sMax = Ps + 64 * PS_STR;           // [64][2]
    float* sSum = sMax + 128;                 // [64][2]

    const int i0   = blockIdx.x * 64;
    const int h    = blockIdx.y;
    const int b    = blockIdx.z;
    const int tid  = threadIdx.x;
    const int lane = tid & 31;
    const int warp = tid >> 5;
    const int mstrip = warp >> 1;
    const int nhalf  = warp & 1;
    const int qd = lane >> 2;
    const int qq = lane & 3;

    const int row0 = 16 * mstrip + qd;
    const int row1 = row0 + 8;

    // Copy slots: Sg tile rows (i), 64 cols (j) = 16 cp16/row-chunked
    const int sc = (tid & 15) * 4;            // col chunk
    const int sr = tid >> 4;                  // rows sr, sr+16, sr+32, sr+48
    const uint32_t SgA  = (uint32_t)__cvta_generic_to_shared(Sg);
    const uint32_t VsA0 = (uint32_t)__cvta_generic_to_shared(Vs0);
    const uint32_t VsA1 = (uint32_t)__cvta_generic_to_shared(Vs1);

    // Prologue: async-copy Sg(0) and V(0)
#pragma unroll
    for (int k = 0; k < KG; k++)
#pragma unroll
        for (int i = 0; i < 4; i++) {
            const int r = sr + i * 16;
            cp16(SgA + (uint32_t)((k * 64 + r) * SG_STR + sc) * 4,
                 &g_gl[((size_t)((b * KG + k) * SEQ + i0 + r)) * SEQ + 0 + sc]);
        }
#pragma unroll
    for (int i = 0; i < 4; i++) {
        const int r = sr + i * 16;
        cp16(VsA0 + (uint32_t)(r * VS_STR + sc) * 4,
             &g_v[((size_t)(b * SEQ + 0 + r)) * DIM + h * HD + sc]);
    }
    cp_commit();

    // mixw = softmax(mix_logits[h,:]) * HEAD_DIM^-0.5
    float ml0 = mixl[h * KG + 0], ml1 = mixl[h * KG + 1];
    float ml2 = mixl[h * KG + 2], ml3 = mixl[h * KG + 3];
    float mm = fmaxf(fmaxf(ml0, ml1), fmaxf(ml2, ml3));
    float e0 = expf(ml0 - mm), e1 = expf(ml1 - mm);
    float e2 = expf(ml2 - mm), e3 = expf(ml3 - mm);
    float inv_es = 0.125f / (e0 + e1 + e2 + e3);
    const float mw0 = e0 * inv_es, mw1 = e1 * inv_es;
    const float mw2 = e2 * inv_es, mw3 = e3 * inv_es;

    float O[4][4];
#pragma unroll
    for (int nt = 0; nt < 4; nt++)
#pragma unroll
        for (int c = 0; c < 4; c++) O[nt][c] = 0.f;
    float m_0 = -INFINITY, m_1 = -INFINITY, l_0 = 0.f, l_1 = 0.f;

    const uint32_t* Psu = (const uint32_t*)Ps;
    const uint32_t* pa0 = Psu + row0 * PS_STR + qq;
    const uint32_t* pa1 = Psu + row1 * PS_STR + qq;

    for (int j0 = 0; j0 < SEQ; j0 += 64) {
        const int vbuf = (j0 >> 6) & 1;
        const uint32_t* Vsu = (const uint32_t*)(vbuf ? Vs1 : Vs0);
        const bool more = (j0 + 64 < SEQ);

        cp_wait_all();       // Sg(j), V(j) landed
        __syncthreads();

        // Prefetch V(j+1) into the other buffer
        if (more) {
            const uint32_t dstA = vbuf ? VsA0 : VsA1;
#pragma unroll
            for (int i = 0; i < 4; i++) {
                const int r = sr + i * 16;
                cp16(dstA + (uint32_t)(r * VS_STR + sc) * 4,
                     &g_v[((size_t)(b * SEQ + j0 + 64 + r)) * DIM + h * HD + sc]);
            }
            cp_commit();
        }

        // ---- S = sum_k mixw[k] * Sg_k ----
        float S[4][4];
#pragma unroll
        for (int nt = 0; nt < 4; nt++) {
            const int col = 32 * nhalf + nt * 8 + 2 * qq;
            const float* p0 = &Sg[row0 * SG_STR + col];
            const float* p1 = &Sg[row1 * SG_STR + col];
            float2 a0 = *(const float2*)(p0);
            float2 a1 = *(const float2*)(p1);
            float2 b0 = *(const float2*)(p0 + 64 * SG_STR);
            float2 b1 = *(const float2*)(p1 + 64 * SG_STR);
            float2 c0 = *(const float2*)(p0 + 128 * SG_STR);
            float2 c1 = *(const float2*)(p1 + 128 * SG_STR);
            float2 d0 = *(const float2*)(p0 + 192 * SG_STR);
            float2 d1 = *(const float2*)(p1 + 192 * SG_STR);
            S[nt][0] = mw0 * a0.x + mw1 * b0.x + mw2 * c0.x + mw3 * d0.x;
            S[nt][1] = mw0 * a0.y + mw1 * b0.y + mw2 * c0.y + mw3 * d0.y;
            S[nt][2] = mw0 * a1.x + mw1 * b1.x + mw2 * c1.x + mw3 * d1.x;
            S[nt][3] = mw0 * a1.y + mw1 * b1.y + mw2 * c1.y + mw3 * d1.y;
        }

        // strip max + stats exchange
        float mx0 = fmaxf(S[0][0], S[0][1]), mx1 = fmaxf(S[0][2], S[0][3]);
#pragma unroll
        for (int nt = 1; nt < 4; nt++) {
            mx0 = fmaxf(mx0, fmaxf(S[nt][0], S[nt][1]));
            mx1 = fmaxf(mx1, fmaxf(S[nt][2], S[nt][3]));
        }
        mx0 = fmaxf(mx0, __shfl_xor_sync(0xffffffffu, mx0, 1));
        mx0 = fmaxf(mx0, __shfl_xor_sync(0xffffffffu, mx0, 2));
        mx1 = fmaxf(mx1, __shfl_xor_sync(0xffffffffu, mx1, 1));
        mx1 = fmaxf(mx1, __shfl_xor_sync(0xffffffffu, mx1, 2));
        if (qq == 0) {
            sMax[row0 * 2 + nhalf] = mx0;
            sMax[row1 * 2 + nhalf] = mx1;
        }
        __syncthreads();     // all Sg reads done AND sMax written

        // Prefetch Sg(j+1) (single buffer; overlaps softmax + AV)
        if (more) {
#pragma unroll
            for (int k = 0; k < KG; k++)
#pragma unroll
                for (int i = 0; i < 4; i++) {
                    const int r = sr + i * 16;
                    cp16(SgA + (uint32_t)((k * 64 + r) * SG_STR + sc) * 4,
                         &g_gl[((size_t)((b * KG + k) * SEQ + i0 + r)) * SEQ + j0 + 64 + sc]);
                }
            cp_commit();
        }

        const float tm0 = fmaxf(sMax[row0 * 2], sMax[row0 * 2 + 1]);
        const float tm1 = fmaxf(sMax[row1 * 2], sMax[row1 * 2 + 1]);
        const float mn0 = fmaxf(m_0, tm0), mn1 = fmaxf(m_1, tm1);
        const float corr0 = __expf(m_0 - mn0), corr1 = __expf(m_1 - mn1);
        m_0 = mn0; m_1 = mn1;

        float rs0 = 0.f, rs1 = 0.f;
#pragma unroll
        for (int nt = 0; nt < 4; nt++) {
            const float p0 = __expf(S[nt][0] - mn0);
            const float p1 = __expf(S[nt][1] - mn0);
            const float p2 = __expf(S[nt][2] - mn1);
            const float p3 = __expf(S[nt][3] - mn1);
            rs0 += p0 + p1; rs1 += p2 + p3;
            const int col = 32 * nhalf + nt * 8 + 2 * qq;
            uint2 w0, w1;
            w0.x = f2tf(p0); w0.y = f2tf(p1);
            w1.x = f2tf(p2); w1.y = f2tf(p3);
            *(uint2*)&Ps[row0 * PS_STR + col] = w0;
            *(uint2*)&Ps[row1 * PS_STR + col] = w1;
            O[nt][0] *= corr0; O[nt][1] *= corr0;
            O[nt][2] *= corr1; O[nt][3] *= corr1;
        }
        rs0 += __shfl_xor_sync(0xffffffffu, rs0, 1);
        rs0 += __shfl_xor_sync(0xffffffffu, rs0, 2);
        rs1 += __shfl_xor_sync(0xffffffffu, rs1, 1);
        rs1 += __shfl_xor_sync(0xffffffffu, rs1, 2);
        if (qq == 0) {
            sSum[row0 * 2 + nhalf] = rs0;
            sSum[row1 * 2 + nhalf] = rs1;
        }
        __syncthreads();     // Ps complete + sSum written
        l_0 = l_0 * corr0 + sSum[row0 * 2] + sSum[row0 * 2 + 1];
        l_1 = l_1 * corr1 + sSum[row1 * 2] + sSum[row1 * 2 + 1];

        // ---- O += P V ----
#pragma unroll
        for (int k0 = 0; k0 < 64; k0 += 8) {
            uint32_t a[4];
            a[0] = pa0[k0]; a[1] = pa1[k0];
            a[2] = pa0[k0 + 4]; a[3] = pa1[k0 + 4];
#pragma unroll
            for (int nt = 0; nt < 4; nt++) {
                const int d = 32 * nhalf + nt * 8 + qd;
                uint32_t bf[2];
                bf[0] = Vsu[(k0 + qq) * VS_STR + d];
                bf[1] = Vsu[(k0 + qq + 4) * VS_STR + d];
                mma_tf32(O[nt], a, bf);
            }
        }
    }

    // Epilogue: normalize, write ctx (B,N,768) fp32
    const float inv0 = 1.f / l_0, inv1 = 1.f / l_1;
    const size_t r0off = ((size_t)(b * SEQ + i0 + row0)) * DIM + h * HD;
    const size_t r1off = ((size_t)(b * SEQ + i0 + row1)) * DIM + h * HD;
#pragma unroll
    for (int nt = 0; nt < 4; nt++) {
        const int col = 32 * nhalf + nt * 8 + 2 * qq;
        float2 o0; o0.x = O[nt][0] * inv0; o0.y = O[nt][1] * inv0;
        float2 o1; o1.x = O[nt][2] * inv1; o1.y = O[nt][3] * inv1;
        *(float2*)&ctx[r0off + col] = o0;
        *(float2*)&ctx[r1off + col] = o1;
    }
}

// ---------------------------------------------------------------------------
// Launch
// ---------------------------------------------------------------------------
extern "C" void kernel_launch(void* const* d_in, const int* in_sizes, int n_in,
                              void* d_out, int out_size)
{
    const float* x      = (const float*)d_in[0];
    const float* w_qkv  = (const float*)d_in[1];
    const float* mixl   = (const float*)d_in[2];
    const float* w_v    = (const float*)d_in[3];
    const float* w_proj = (const float*)d_in[4];
    const float* b_proj = (const float*)d_in[5];
    float* out = (float*)d_out;

    float *qk, *v, *ctx, *gl;
    cudaGetSymbolAddress((void**)&qk,  g_qk);
    cudaGetSymbolAddress((void**)&v,   g_v);
    cudaGetSymbolAddress((void**)&ctx, g_ctx);
    cudaGetSymbolAddress((void**)&gl,  g_gl);

    const int attn_smem = (4 * 64 * SG_STR + 2 * 64 * VS_STR + 64 * PS_STR + 256) * (int)sizeof(float);
    cudaFuncSetAttribute(fish_mix_attn, cudaFuncAttributeMaxDynamicSharedMemorySize, attn_smem);

    // 1) qk = x @ w_qkv[0:512]^T  -> tf32 bits
    tf32_gemm_nt<512, true, false><<<dim3(4, 64), 256>>>(x, w_qkv, nullptr, qk);
    // 2) v = x @ w_v^T            -> tf32 bits
    tf32_gemm_nt<768, true, false><<<dim3(6, 64), 256>>>(x, w_v, nullptr, v);
    // A) global logits per (b, k-head): gl = q_k . k_k^T  (fp32 raw)
    gl_gemm<<<dim3(8, 8, BB * KG), 256>>>(qk, gl);
    // B) mix + softmax + AV
    fish_mix_attn<<<dim3(SEQ / 64, NH, BB), 256, attn_smem>>>(mixl, ctx);
    // 4) out = ctx @ w_proj^T + b_proj (fp32 out)
    tf32_gemm_nt<768, false, true><<<dim3(6, 64), 256>>>(ctx, w_proj, b_proj, out);
}

// round 7
// speedup vs baseline: 4.6048x; 1.0768x over previous
#include <cuda_runtime.h>
#include <math.h>
#include <stdint.h>

// Problem constants
#define BB   8
#define SEQ  1024
#define DIM  768
#define NH   12
#define KG   4
#define HD   64
#define MTOT (BB*SEQ)     // 8192

// Scratch (static device globals — no runtime allocation allowed)
// g_qk / g_v hold TF32 bit patterns (converted in GEMM epilogue).
__device__ float g_qk[(size_t)MTOT * 512];   // per row: [0,256)=q heads, [256,512)=k heads
__device__ float g_v [(size_t)MTOT * DIM];
__device__ float g_ctx[(size_t)MTOT * DIM];
__device__ float g_gl[(size_t)BB * KG * SEQ * SEQ];   // raw global logits q_k . k_k^T

// ---------------------------------------------------------------------------
// TF32 / cp.async helpers
// ---------------------------------------------------------------------------
__device__ __forceinline__ uint32_t f2tf(float x) {
    uint32_t r;
    asm("cvt.rna.tf32.f32 %0, %1;" : "=r"(r) : "f"(x));
    return r;
}

__device__ __forceinline__ void mma_tf32(float* d, const uint32_t* a, const uint32_t* b) {
    asm volatile(
        "mma.sync.aligned.m16n8k8.row.col.f32.tf32.tf32.f32 "
        "{%0,%1,%2,%3}, {%4,%5,%6,%7}, {%8,%9}, {%0,%1,%2,%3};"
        : "+f"(d[0]), "+f"(d[1]), "+f"(d[2]), "+f"(d[3])
        : "r"(a[0]), "r"(a[1]), "r"(a[2]), "r"(a[3]), "r"(b[0]), "r"(b[1]));
}

__device__ __forceinline__ void cp16(uint32_t smem_dst, const void* gsrc) {
    asm volatile("cp.async.cg.shared.global [%0], [%1], 16;"
                 :: "r"(smem_dst), "l"(gsrc));
}
__device__ __forceinline__ void cp_commit() {
    asm volatile("cp.async.commit_group;");
}
__device__ __forceinline__ void cp_wait_all() {
    asm volatile("cp.async.wait_group 0;");
}

// ---------------------------------------------------------------------------
// TF32 tensor-core GEMM: C[M, NC] = A[M, 768] @ W[NC, 768]^T (+ bias).
// ---------------------------------------------------------------------------
#define GS_STR 36

template<int NC, bool OUT_TF32, bool BIAS>
__global__ void __launch_bounds__(256, 2) tf32_gemm_nt(const float* __restrict__ A,
                                                       const float* __restrict__ W,
                                                       const float* __restrict__ bias,
                                                       float* __restrict__ C)
{
    __shared__ uint32_t As[128 * GS_STR];
    __shared__ uint32_t Ws[128 * GS_STR];

    const int m0  = blockIdx.y * 128;
    const int n0  = blockIdx.x * 128;
    const int tid = threadIdx.x;
    const int lane = tid & 31;
    const int warp = tid >> 5;
    const int warp_m = warp >> 2;
    const int warp_n = warp & 3;
    const int qd = lane >> 2;
    const int qq = lane & 3;

    const int lr = tid >> 1;
    const int lc = (tid & 1) * 16;

    const float* Ap = A + (size_t)(m0 + lr) * DIM + lc;
    const float* Wp = W + (size_t)(n0 + lr) * DIM + lc;
    uint32_t* Asd = &As[lr * GS_STR + lc];
    uint32_t* Wsd = &Ws[lr * GS_STR + lc];

    float acc[4][4][4];
#pragma unroll
    for (int mf = 0; mf < 4; mf++)
#pragma unroll
        for (int nf = 0; nf < 4; nf++)
#pragma unroll
            for (int c = 0; c < 4; c++) acc[mf][nf][c] = 0.f;

    float4 av[4], wv[4];
#pragma unroll
    for (int i = 0; i < 4; i++) {
        av[i] = *(const float4*)(Ap + i * 4);
        wv[i] = *(const float4*)(Wp + i * 4);
    }

    for (int k0 = 0; k0 < DIM; k0 += 32) {
        __syncthreads();
#pragma unroll
        for (int i = 0; i < 4; i++) {
            uint4 at, wt;
            at.x = f2tf(av[i].x); at.y = f2tf(av[i].y);
            at.z = f2tf(av[i].z); at.w = f2tf(av[i].w);
            wt.x = f2tf(wv[i].x); wt.y = f2tf(wv[i].y);
            wt.z = f2tf(wv[i].z); wt.w = f2tf(wv[i].w);
            *(uint4*)(Asd + i * 4) = at;
            *(uint4*)(Wsd + i * 4) = wt;
        }
        __syncthreads();

        if (k0 + 32 < DIM) {
#pragma unroll
            for (int i = 0; i < 4; i++) {
                av[i] = *(const float4*)(Ap + k0 + 32 + i * 4);
                wv[i] = *(const float4*)(Wp + k0 + 32 + i * 4);
            }
        }

#pragma unroll
        for (int kk = 0; kk < 32; kk += 8) {
            uint32_t a[4][4];
#pragma unroll
            for (int mf = 0; mf < 4; mf++) {
                const int base = warp_m * 64 + mf * 16 + qd;
                a[mf][0] = As[base * GS_STR + kk + qq];
                a[mf][1] = As[(base + 8) * GS_STR + kk + qq];
                a[mf][2] = As[base * GS_STR + kk + qq + 4];
                a[mf][3] = As[(base + 8) * GS_STR + kk + qq + 4];
            }
#pragma unroll
            for (int nf = 0; nf < 4; nf++) {
                const int col = warp_n * 32 + nf * 8 + qd;
                uint32_t bfr[2];
                bfr[0] = Ws[col * GS_STR + kk + qq];
                bfr[1] = Ws[col * GS_STR + kk + qq + 4];
#pragma unroll
                for (int mf = 0; mf < 4; mf++)
                    mma_tf32(acc[mf][nf], a[mf], bfr);
            }
        }
    }

#pragma unroll
    for (int mf = 0; mf < 4; mf++) {
        const int row0 = m0 + warp_m * 64 + mf * 16 + qd;
        const int row1 = row0 + 8;
#pragma unroll
        for (int nf = 0; nf < 4; nf++) {
            const int col = n0 + warp_n * 32 + nf * 8 + 2 * qq;
            float2 o0, o1;
            o0.x = acc[mf][nf][0]; o0.y = acc[mf][nf][1];
            o1.x = acc[mf][nf][2]; o1.y = acc[mf][nf][3];
            if (BIAS) {
                const float2 bv = *(const float2*)&bias[col];
                o0.x += bv.x; o0.y += bv.y;
                o1.x += bv.x; o1.y += bv.y;
            }
            if (OUT_TF32) {
                o0.x = __uint_as_float(f2tf(o0.x)); o0.y = __uint_as_float(f2tf(o0.y));
                o1.x = __uint_as_float(f2tf(o1.x)); o1.y = __uint_as_float(f2tf(o1.y));
            }
            *(float2*)&C[(size_t)row0 * NC + col] = o0;
            *(float2*)&C[(size_t)row1 * NC + col] = o1;
        }
    }
}

// ---------------------------------------------------------------------------
// Kernel A: global logits. For (b, kh): gl[i,j] = q_kh[i] . k_kh[j], K=64.
// ---------------------------------------------------------------------------
__global__ void __launch_bounds__(256, 2) gl_gemm(const float* __restrict__ QK,
                                                  float* __restrict__ GL)
{
    __shared__ uint32_t As[128 * GS_STR];
    __shared__ uint32_t Ws[128 * GS_STR];

    const int b  = blockIdx.z >> 2;
    const int kh = blockIdx.z & 3;
    const int m0 = blockIdx.y * 128;
    const int n0 = blockIdx.x * 128;
    const int tid = threadIdx.x;
    const int lane = tid & 31;
    const int warp = tid >> 5;
    const int warp_m = warp >> 2;
    const int warp_n = warp & 3;
    const int qd = lane >> 2;
    const int qq = lane & 3;

    const int lr = tid >> 1;
    const int lc = (tid & 1) * 16;

    const uint32_t* Ap = (const uint32_t*)QK + (size_t)(b * SEQ + m0 + lr) * 512 + kh * HD + lc;
    const uint32_t* Wp = (const uint32_t*)QK + (size_t)(b * SEQ + n0 + lr) * 512 + 256 + kh * HD + lc;
    uint32_t* Asd = &As[lr * GS_STR + lc];
    uint32_t* Wsd = &Ws[lr * GS_STR + lc];

    float acc[4][4][4];
#pragma unroll
    for (int mf = 0; mf < 4; mf++)
#pragma unroll
        for (int nf = 0; nf < 4; nf++)
#pragma unroll
            for (int c = 0; c < 4; c++) acc[mf][nf][c] = 0.f;

    uint4 av[4], wv[4];
#pragma unroll
    for (int i = 0; i < 4; i++) {
        av[i] = *(const uint4*)(Ap + i * 4);
        wv[i] = *(const uint4*)(Wp + i * 4);
    }

#pragma unroll
    for (int k0 = 0; k0 < HD; k0 += 32) {
        __syncthreads();
#pragma unroll
        for (int i = 0; i < 4; i++) {
            *(uint4*)(Asd + i * 4) = av[i];
            *(uint4*)(Wsd + i * 4) = wv[i];
        }
        __syncthreads();

        if (k0 + 32 < HD) {
#pragma unroll
            for (int i = 0; i < 4; i++) {
                av[i] = *(const uint4*)(Ap + k0 + 32 + i * 4);
                wv[i] = *(const uint4*)(Wp + k0 + 32 + i * 4);
            }
        }

#pragma unroll
        for (int kk = 0; kk < 32; kk += 8) {
            uint32_t a[4][4];
#pragma unroll
            for (int mf = 0; mf < 4; mf++) {
                const int base = warp_m * 64 + mf * 16 + qd;
                a[mf][0] = As[base * GS_STR + kk + qq];
                a[mf][1] = As[(base + 8) * GS_STR + kk + qq];
                a[mf][2] = As[base * GS_STR + kk + qq + 4];
                a[mf][3] = As[(base + 8) * GS_STR + kk + qq + 4];
            }
#pragma unroll
            for (int nf = 0; nf < 4; nf++) {
                const int col = warp_n * 32 + nf * 8 + qd;
                uint32_t bfr[2];
                bfr[0] = Ws[col * GS_STR + kk + qq];
                bfr[1] = Ws[col * GS_STR + kk + qq + 4];
#pragma unroll
                for (int mf = 0; mf < 4; mf++)
                    mma_tf32(acc[mf][nf], a[mf], bfr);
            }
        }
    }

    float* Cp = GL + (size_t)blockIdx.z * SEQ * SEQ;
#pragma unroll
    for (int mf = 0; mf < 4; mf++) {
        const int row0 = m0 + warp_m * 64 + mf * 16 + qd;
        const int row1 = row0 + 8;
#pragma unroll
        for (int nf = 0; nf < 4; nf++) {
            const int col = n0 + warp_n * 32 + nf * 8 + 2 * qq;
            float2 o0, o1;
            o0.x = acc[mf][nf][0]; o0.y = acc[mf][nf][1];
            o1.x = acc[mf][nf][2]; o1.y = acc[mf][nf][3];
            *(float2*)&Cp[(size_t)row0 * SEQ + col] = o0;
            *(float2*)&Cp[(size_t)row1 * SEQ + col] = o1;
        }
    }
}

// ---------------------------------------------------------------------------
// Kernel B: mix + softmax + AV, TWO heads per CTA (512 threads).
// Warps 0-7 -> head 2y, warps 8-15 -> head 2y+1; Sg smem shared by both.
// ---------------------------------------------------------------------------
#define SG_STR 68
#define VS_STR 72
#define PS_STR 68

__global__ void __launch_bounds__(512) fish_mix_attn(const float* __restrict__ mixl,
                                                     float* __restrict__ ctx)
{
    extern __shared__ float sm[];
    float* Sg    = sm;                          // [4][64][SG_STR] shared by both heads
    float* VsAll = Sg + 4 * 64 * SG_STR;        // [2 heads][2 buf][64][VS_STR]
    float* PsAll = VsAll + 2 * 2 * 64 * VS_STR; // [2 heads][64][PS_STR]
    float* sMaxA = PsAll + 2 * 64 * PS_STR;     // [2 heads][64][2]
    float* sSumA = sMaxA + 256;                 // [2 heads][64][2]

    const int i0   = blockIdx.x * 64;
    const int b    = blockIdx.z;
    const int tid  = threadIdx.x;
    const int hh   = tid >> 8;                  // 0 or 1: head half
    const int t    = tid & 255;                 // index within half
    const int h    = blockIdx.y * 2 + hh;
    const int lane = tid & 31;
    const int warp8 = (tid >> 5) & 7;           // warp within half
    const int mstrip = warp8 >> 1;
    const int nhalf  = warp8 & 1;
    const int qd = lane >> 2;
    const int qq = lane & 3;

    const int row0 = 16 * mstrip + qd;
    const int row1 = row0 + 8;

    float* Vs0  = VsAll + hh * 2 * 64 * VS_STR;
    float* Vs1  = Vs0 + 64 * VS_STR;
    float* Ps   = PsAll + hh * 64 * PS_STR;
    float* sMax = sMaxA + hh * 128;
    float* sSum = sSumA + hh * 128;

    // Sg copy slots: all 512 threads. 16 col-chunks x 32 rows; 2 rows per k-head.
    const int gc = (tid & 15) * 4;
    const int gr = tid >> 4;                    // 0..31
    // V copy slots: per half. 16 col-chunks x 16 rows; 4 rows each.
    const int vc = (t & 15) * 4;
    const int vr = t >> 4;                      // 0..15
    const uint32_t SgA  = (uint32_t)__cvta_generic_to_shared(Sg);
    const uint32_t VsA0 = (uint32_t)__cvta_generic_to_shared(Vs0);
    const uint32_t VsA1 = (uint32_t)__cvta_generic_to_shared(Vs1);

    // Prologue: async-copy Sg(0) (whole CTA) and V(0) (per half)
#pragma unroll
    for (int k = 0; k < KG; k++)
#pragma unroll
        for (int i = 0; i < 2; i++) {
            const int r = gr + i * 32;
            cp16(SgA + (uint32_t)((k * 64 + r) * SG_STR + gc) * 4,
                 &g_gl[((size_t)((b * KG + k) * SEQ + i0 + r)) * SEQ + 0 + gc]);
        }
#pragma unroll
    for (int i = 0; i < 4; i++) {
        const int r = vr + i * 16;
        cp16(VsA0 + (uint32_t)(r * VS_STR + vc) * 4,
             &g_v[((size_t)(b * SEQ + 0 + r)) * DIM + h * HD + vc]);
    }
    cp_commit();

    // mixw = softmax(mix_logits[h,:]) * HEAD_DIM^-0.5
    float ml0 = mixl[h * KG + 0], ml1 = mixl[h * KG + 1];
    float ml2 = mixl[h * KG + 2], ml3 = mixl[h * KG + 3];
    float mm = fmaxf(fmaxf(ml0, ml1), fmaxf(ml2, ml3));
    float e0 = expf(ml0 - mm), e1 = expf(ml1 - mm);
    float e2 = expf(ml2 - mm), e3 = expf(ml3 - mm);
    float inv_es = 0.125f / (e0 + e1 + e2 + e3);
    const float mw0 = e0 * inv_es, mw1 = e1 * inv_es;
    const float mw2 = e2 * inv_es, mw3 = e3 * inv_es;

    float O[4][4];
#pragma unroll
    for (int nt = 0; nt < 4; nt++)
#pragma unroll
        for (int c = 0; c < 4; c++) O[nt][c] = 0.f;
    float m_0 = -INFINITY, m_1 = -INFINITY, l_0 = 0.f, l_1 = 0.f;

    const uint32_t* Psu = (const uint32_t*)Ps;
    const uint32_t* pa0 = Psu + row0 * PS_STR + qq;
    const uint32_t* pa1 = Psu + row1 * PS_STR + qq;

    for (int j0 = 0; j0 < SEQ; j0 += 64) {
        const int vbuf = (j0 >> 6) & 1;
        const uint32_t* Vsu = (const uint32_t*)(vbuf ? Vs1 : Vs0);
        const bool more = (j0 + 64 < SEQ);

        cp_wait_all();       // Sg(j), V(j) landed
        __syncthreads();

        // Prefetch V(j+1) into the other buffer (per half)
        if (more) {
            const uint32_t dstA = vbuf ? VsA0 : VsA1;
#pragma unroll
            for (int i = 0; i < 4; i++) {
                const int r = vr + i * 16;
                cp16(dstA + (uint32_t)(r * VS_STR + vc) * 4,
                     &g_v[((size_t)(b * SEQ + j0 + 64 + r)) * DIM + h * HD + vc]);
            }
            cp_commit();
        }

        // ---- S = sum_k mixw[k] * Sg_k ----
        float S[4][4];
#pragma unroll
        for (int nt = 0; nt < 4; nt++) {
            const int col = 32 * nhalf + nt * 8 + 2 * qq;
            const float* p0 = &Sg[row0 * SG_STR + col];
            const float* p1 = &Sg[row1 * SG_STR + col];
            float2 a0 = *(const float2*)(p0);
            float2 a1 = *(const float2*)(p1);
            float2 b0 = *(const float2*)(p0 + 64 * SG_STR);
            float2 b1 = *(const float2*)(p1 + 64 * SG_STR);
            float2 c0 = *(const float2*)(p0 + 128 * SG_STR);
            float2 c1 = *(const float2*)(p1 + 128 * SG_STR);
            float2 d0 = *(const float2*)(p0 + 192 * SG_STR);
            float2 d1 = *(const float2*)(p1 + 192 * SG_STR);
            S[nt][0] = mw0 * a0.x + mw1 * b0.x + mw2 * c0.x + mw3 * d0.x;
            S[nt][1] = mw0 * a0.y + mw1 * b0.y + mw2 * c0.y + mw3 * d0.y;
            S[nt][2] = mw0 * a1.x + mw1 * b1.x + mw2 * c1.x + mw3 * d1.x;
            S[nt][3] = mw0 * a1.y + mw1 * b1.y + mw2 * c1.y + mw3 * d1.y;
        }

        // strip max + stats exchange (per head)
        float mx0 = fmaxf(S[0][0], S[0][1]), mx1 = fmaxf(S[0][2], S[0][3]);
#pragma unroll
        for (int nt = 1; nt < 4; nt++) {
            mx0 = fmaxf(mx0, fmaxf(S[nt][0], S[nt][1]));
            mx1 = fmaxf(mx1, fmaxf(S[nt][2], S[nt][3]));
        }
        mx0 = fmaxf(mx0, __shfl_xor_sync(0xffffffffu, mx0, 1));
        mx0 = fmaxf(mx0, __shfl_xor_sync(0xffffffffu, mx0, 2));
        mx1 = fmaxf(mx1, __shfl_xor_sync(0xffffffffu, mx1, 1));
        mx1 = fmaxf(mx1, __shfl_xor_sync(0xffffffffu, mx1, 2));
        if (qq == 0) {
            sMax[row0 * 2 + nhalf] = mx0;
            sMax[row1 * 2 + nhalf] = mx1;
        }
        __syncthreads();     // all Sg reads done (both heads) AND sMax written

        // Prefetch Sg(j+1) (single buffer; overlaps softmax + AV; whole CTA)
        if (more) {
#pragma unroll
            for (int k = 0; k < KG; k++)
#pragma unroll
                for (int i = 0; i < 2; i++) {
                    const int r = gr + i * 32;
                    cp16(SgA + (uint32_t)((k * 64 + r) * SG_STR + gc) * 4,
                         &g_gl[((size_t)((b * KG + k) * SEQ + i0 + r)) * SEQ + j0 + 64 + gc]);
                }
            cp_commit();
        }

        const float tm0 = fmaxf(sMax[row0 * 2], sMax[row0 * 2 + 1]);
        const float tm1 = fmaxf(sMax[row1 * 2], sMax[row1 * 2 + 1]);
        const float mn0 = fmaxf(m_0, tm0), mn1 = fmaxf(m_1, tm1);
        const float corr0 = __expf(m_0 - mn0), corr1 = __expf(m_1 - mn1);
        m_0 = mn0; m_1 = mn1;

        float rs0 = 0.f, rs1 = 0.f;
#pragma unroll
        for (int nt = 0; nt < 4; nt++) {
            const float p0 = __expf(S[nt][0] - mn0);
            const float p1 = __expf(S[nt][1] - mn0);
            const float p2 = __expf(S[nt][2] - mn1);
            const float p3 = __expf(S[nt][3] - mn1);
            rs0 += p0 + p1; rs1 += p2 + p3;
            const int col = 32 * nhalf + nt * 8 + 2 * qq;
            uint2 w0, w1;
            w0.x = f2tf(p0); w0.y = f2tf(p1);
            w1.x = f2tf(p2); w1.y = f2tf(p3);
            *(uint2*)&Ps[row0 * PS_STR + col] = w0;
            *(uint2*)&Ps[row1 * PS_STR + col] = w1;
            O[nt][0] *= corr0; O[nt][1] *= corr0;
            O[nt][2] *= corr1; O[nt][3] *= corr1;
        }
        rs0 += __shfl_xor_sync(0xffffffffu, rs0, 1);
        rs0 += __shfl_xor_sync(0xffffffffu, rs0, 2);
        rs1 += __shfl_xor_sync(0xffffffffu, rs1, 1);
        rs1 += __shfl_xor_sync(0xffffffffu, rs1, 2);
        if (qq == 0) {
            sSum[row0 * 2 + nhalf] = rs0;
            sSum[row1 * 2 + nhalf] = rs1;
        }
        __syncthreads();     // Ps complete + sSum written
        l_0 = l_0 * corr0 + sSum[row0 * 2] + sSum[row0 * 2 + 1];
        l_1 = l_1 * corr1 + sSum[row1 * 2] + sSum[row1 * 2 + 1];

        // ---- O += P V ----
#pragma unroll
        for (int k0 = 0; k0 < 64; k0 += 8) {
            uint32_t a[4];
            a[0] = pa0[k0]; a[1] = pa1[k0];
            a[2] = pa0[k0 + 4]; a[3] = pa1[k0 + 4];
#pragma unroll
            for (int nt = 0; nt < 4; nt++) {
                const int d = 32 * nhalf + nt * 8 + qd;
                uint32_t bf[2];
                bf[0] = Vsu[(k0 + qq) * VS_STR + d];
                bf[1] = Vsu[(k0 + qq + 4) * VS_STR + d];
                mma_tf32(O[nt], a, bf);
            }
        }
    }

    // Epilogue: normalize, write ctx (B,N,768) fp32
    const float inv0 = 1.f / l_0, inv1 = 1.f / l_1;
    const size_t r0off = ((size_t)(b * SEQ + i0 + row0)) * DIM + h * HD;
    const size_t r1off = ((size_t)(b * SEQ + i0 + row1)) * DIM + h * HD;
#pragma unroll
    for (int nt = 0; nt < 4; nt++) {
        const int col = 32 * nhalf + nt * 8 + 2 * qq;
        float2 o0; o0.x = O[nt][0] * inv0; o0.y = O[nt][1] * inv0;
        float2 o1; o1.x = O[nt][2] * inv1; o1.y = O[nt][3] * inv1;
        *(float2*)&ctx[r0off + col] = o0;
        *(float2*)&ctx[r1off + col] = o1;
    }
}

// ---------------------------------------------------------------------------
// Launch
// ---------------------------------------------------------------------------
extern "C" void kernel_launch(void* const* d_in, const int* in_sizes, int n_in,
                              void* d_out, int out_size)
{
    const float* x      = (const float*)d_in[0];
    const float* w_qkv  = (const float*)d_in[1];
    const float* mixl   = (const float*)d_in[2];
    const float* w_v    = (const float*)d_in[3];
    const float* w_proj = (const float*)d_in[4];
    const float* b_proj = (const float*)d_in[5];
    float* out = (float*)d_out;

    float *qk, *v, *ctx, *gl;
    cudaGetSymbolAddress((void**)&qk,  g_qk);
    cudaGetSymbolAddress((void**)&v,   g_v);
    cudaGetSymbolAddress((void**)&ctx, g_ctx);
    cudaGetSymbolAddress((void**)&gl,  g_gl);

    const int attn_smem = (4 * 64 * SG_STR + 2 * 2 * 64 * VS_STR + 2 * 64 * PS_STR + 512)
                          * (int)sizeof(float);
    cudaFuncSetAttribute(fish_mix_attn, cudaFuncAttributeMaxDynamicSharedMemorySize, attn_smem);

    // 1) qk = x @ w_qkv[0:512]^T  -> tf32 bits
    tf32_gemm_nt<512, true, false><<<dim3(4, 64), 256>>>(x, w_qkv, nullptr, qk);
    // 2) v = x @ w_v^T            -> tf32 bits
    tf32_gemm_nt<768, true, false><<<dim3(6, 64), 256>>>(x, w_v, nullptr, v);
    // A) global logits per (b, k-head): gl = q_k . k_k^T  (fp32 raw)
    gl_gemm<<<dim3(8, 8, BB * KG), 256>>>(qk, gl);
    // B) mix + softmax + AV, 2 heads per CTA
    fish_mix_attn<<<dim3(SEQ / 64, NH / 2, BB), 512, attn_smem>>>(mixl, ctx);
    // 4) out = ctx @ w_proj^T + b_proj (fp32 out)
    tf32_gemm_nt<768, false, true><<<dim3(6, 64), 256>>>(ctx, w_proj, b_proj, out);
}